// round 1
// baseline (speedup 1.0000x reference)
#include <cuda_runtime.h>

// Problem dims
#define BT 16384   // B*T = 8*2048
#define TSEQ 2048
#define DD 512
#define HH 128
#define NK 7
#define FF 512
#define KF 3584    // NK*FF
#define KDIM2 896  // NK*HH

// Scratch (allocation-free rule: __device__ globals)
__device__ float g_rs[BT];
__device__ float g_h[BT * HH];

// ---------------------------------------------------------------------------
// Kernel 1: per-token channel rowsum  rs[t] = sum_d x[t,d]
// one warp per row, 8 warps per block
// ---------------------------------------------------------------------------
__global__ void rowsum_kernel(const float* __restrict__ x) {
    int row  = blockIdx.x * 8 + threadIdx.y;
    int lane = threadIdx.x;
    const float4* xr = (const float4*)(x + (size_t)row * DD);
    float s = 0.f;
#pragma unroll
    for (int j = lane; j < DD / 4; j += 32) {
        float4 v = xr[j];
        s += (v.x + v.y) + (v.z + v.w);
    }
#pragma unroll
    for (int o = 16; o; o >>= 1) s += __shfl_xor_sync(0xffffffffu, s, o);
    if (lane == 0) g_rs[row] = s;
}

// ---------------------------------------------------------------------------
// Kernel 2: GEMM1  h = relu(x @ W1 + b1)   [16384,512]@[512,128]
// BM=128, BN=128(=H), BK=8, 256 threads, 8x8 microtile (4+4 split)
// ---------------------------------------------------------------------------
__global__ __launch_bounds__(256) void gemm1_kernel(
    const float* __restrict__ x, const float* __restrict__ W1,
    const float* __restrict__ b1) {
    __shared__ __align__(16) float As[8][128];
    __shared__ __align__(16) float Bs[8][128];

    int tid = threadIdx.x;
    int rowBase = blockIdx.x * 128;

    int tr = tid >> 4;          // 0..15
    int tc = tid & 15;          // 0..15
    int ar = tid >> 1;          // 0..127   A-load row
    int aseg = (tid & 1) * 4;   // 0 or 4
    int br = tid >> 5;          // 0..7     B-load row
    int bc = (tid & 31) * 4;    // 0..124

    float acc[8][8];
#pragma unroll
    for (int i = 0; i < 8; i++)
#pragma unroll
        for (int j = 0; j < 8; j++) acc[i][j] = 0.f;

    for (int k0 = 0; k0 < DD; k0 += 8) {
        float4 av = *(const float4*)(x + (size_t)(rowBase + ar) * DD + k0 + aseg);
        As[aseg + 0][ar] = av.x;
        As[aseg + 1][ar] = av.y;
        As[aseg + 2][ar] = av.z;
        As[aseg + 3][ar] = av.w;
        float4 bv = *(const float4*)(W1 + (size_t)(k0 + br) * HH + bc);
        *(float4*)&Bs[br][bc] = bv;
        __syncthreads();
#pragma unroll
        for (int kk = 0; kk < 8; kk++) {
            float a[8], b[8];
            *(float4*)&a[0] = *(const float4*)&As[kk][tr * 4];
            *(float4*)&a[4] = *(const float4*)&As[kk][64 + tr * 4];
            *(float4*)&b[0] = *(const float4*)&Bs[kk][tc * 4];
            *(float4*)&b[4] = *(const float4*)&Bs[kk][64 + tc * 4];
#pragma unroll
            for (int i = 0; i < 8; i++)
#pragma unroll
                for (int j = 0; j < 8; j++) acc[i][j] = fmaf(a[i], b[j], acc[i][j]);
        }
        __syncthreads();
    }

    // epilogue: relu(acc + b1) -> g_h
#pragma unroll
    for (int i = 0; i < 8; i++) {
        int rloc = (i < 4) ? (tr * 4 + i) : (64 + tr * 4 + i - 4);
        size_t rowOff = (size_t)(rowBase + rloc) * HH;
#pragma unroll
        for (int half = 0; half < 2; half++) {
            int c0 = half * 64 + tc * 4;
            float4 o;
            o.x = fmaxf(acc[i][half * 4 + 0] + b1[c0 + 0], 0.f);
            o.y = fmaxf(acc[i][half * 4 + 1] + b1[c0 + 1], 0.f);
            o.z = fmaxf(acc[i][half * 4 + 2] + b1[c0 + 2], 0.f);
            o.w = fmaxf(acc[i][half * 4 + 3] + b1[c0 + 3], 0.f);
            *(float4*)&g_h[rowOff + c0] = o;
        }
    }
}

// ---------------------------------------------------------------------------
// Kernel 3: GEMM2 fused dynamic conv + residual
// out[t,f] = x[t,f] + sum_{k,h} (rs[t+k-3]*h[t,h]) * W2[h,k*F+f]
//                   + sum_k rs[t+k-3]*b2[k*F+f]
// A[t, k*128+h] = rs_window * h  built on the fly in the smem load.
// ---------------------------------------------------------------------------
__global__ __launch_bounds__(256) void gemm2_kernel(
    const float* __restrict__ x, const float* __restrict__ W2,
    const float* __restrict__ b2, float* __restrict__ out) {
    __shared__ __align__(16) float As[8][128];
    __shared__ __align__(16) float Bs[8][128];
    __shared__ float rs_s[134];       // rows rowBase-3 .. rowBase+130
    __shared__ float b2_s[NK][128];

    int tid = threadIdx.x;
    int rowBase = blockIdx.y * 128;
    int fBase = blockIdx.x * 128;

    // rs window with batch-boundary zeros (block rows are within one batch: 2048%128==0)
    int bstart = (rowBase / TSEQ) * TSEQ;
    if (tid < 134) {
        int gi = rowBase + tid - 3;
        float v = 0.f;
        if (gi >= bstart && gi < bstart + TSEQ) v = g_rs[gi];
        rs_s[tid] = v;
    }
    for (int idx = tid; idx < NK * 128; idx += 256) {
        int kk = idx >> 7, ff = idx & 127;
        b2_s[kk][ff] = b2[kk * FF + fBase + ff];
    }
    __syncthreads();

    int tr = tid >> 4;
    int tc = tid & 15;
    int ar = tid >> 1;
    int aseg = (tid & 1) * 4;
    int br = tid >> 5;
    int bc = (tid & 31) * 4;

    float acc[8][8];
#pragma unroll
    for (int i = 0; i < 8; i++)
#pragma unroll
        for (int j = 0; j < 8; j++) acc[i][j] = 0.f;

    for (int it = 0; it < KDIM2 / 8; it++) {
        int p0 = it * 8;
        int k = p0 >> 7;        // conv tap (slab of 128 h's per tap)
        int hcol = p0 & 127;
        float scale = rs_s[ar + k];
        float4 av = *(const float4*)(g_h + (size_t)(rowBase + ar) * HH + hcol + aseg);
        As[aseg + 0][ar] = av.x * scale;
        As[aseg + 1][ar] = av.y * scale;
        As[aseg + 2][ar] = av.z * scale;
        As[aseg + 3][ar] = av.w * scale;
        // B[p, f] = W2[hcol+br, k*FF + fBase + bc]
        float4 bv = *(const float4*)(W2 + (size_t)(hcol + br) * KF + k * FF + fBase + bc);
        *(float4*)&Bs[br][bc] = bv;
        __syncthreads();
#pragma unroll
        for (int kk = 0; kk < 8; kk++) {
            float a[8], b[8];
            *(float4*)&a[0] = *(const float4*)&As[kk][tr * 4];
            *(float4*)&a[4] = *(const float4*)&As[kk][64 + tr * 4];
            *(float4*)&b[0] = *(const float4*)&Bs[kk][tc * 4];
            *(float4*)&b[4] = *(const float4*)&Bs[kk][64 + tc * 4];
#pragma unroll
            for (int i = 0; i < 8; i++)
#pragma unroll
                for (int j = 0; j < 8; j++) acc[i][j] = fmaf(a[i], b[j], acc[i][j]);
        }
        __syncthreads();
    }

    // epilogue: + bias window + residual x, write pre-LN y to out
#pragma unroll
    for (int i = 0; i < 8; i++) {
        int rloc = (i < 4) ? (tr * 4 + i) : (64 + tr * 4 + i - 4);
        int grow = rowBase + rloc;
#pragma unroll
        for (int half = 0; half < 2; half++) {
            int c0 = half * 64 + tc * 4;
            float v[4];
#pragma unroll
            for (int j = 0; j < 4; j++) {
                float bias = 0.f;
#pragma unroll
                for (int k = 0; k < NK; k++)
                    bias = fmaf(rs_s[rloc + k], b2_s[k][c0 + j], bias);
                v[j] = acc[i][half * 4 + j] + bias;
            }
            float4 xr = *(const float4*)(x + (size_t)grow * DD + fBase + c0);
            float4 o;
            o.x = v[0] + xr.x;
            o.y = v[1] + xr.y;
            o.z = v[2] + xr.z;
            o.w = v[3] + xr.w;
            *(float4*)(out + (size_t)grow * FF + fBase + c0) = o;
        }
    }
}

// ---------------------------------------------------------------------------
// Kernel 4: in-place LayerNorm(eps=1e-3) + relu over F=512, one row per block
// ---------------------------------------------------------------------------
__global__ __launch_bounds__(128) void ln_kernel(
    float* __restrict__ out, const float* __restrict__ gamma,
    const float* __restrict__ beta) {
    int row = blockIdx.x;
    int tid = threadIdx.x;  // 128 threads, 4 floats each
    float4 v = *(const float4*)(out + (size_t)row * FF + tid * 4);

    float s = (v.x + v.y) + (v.z + v.w);
    float s2 = (v.x * v.x + v.y * v.y) + (v.z * v.z + v.w * v.w);
#pragma unroll
    for (int o = 16; o; o >>= 1) {
        s  += __shfl_xor_sync(0xffffffffu, s, o);
        s2 += __shfl_xor_sync(0xffffffffu, s2, o);
    }
    __shared__ float sred[8];
    int w = tid >> 5;
    if ((tid & 31) == 0) { sred[w] = s; sred[4 + w] = s2; }
    __syncthreads();
    s  = (sred[0] + sred[1]) + (sred[2] + sred[3]);
    s2 = (sred[4] + sred[5]) + (sred[6] + sred[7]);

    float mean = s * (1.f / FF);
    float var = s2 * (1.f / FF) - mean * mean;
    float inv = rsqrtf(var + 1e-3f);

    float4 g = *(const float4*)(gamma + tid * 4);
    float4 b = *(const float4*)(beta + tid * 4);
    float4 o;
    o.x = fmaxf((v.x - mean) * inv * g.x + b.x, 0.f);
    o.y = fmaxf((v.y - mean) * inv * g.y + b.y, 0.f);
    o.z = fmaxf((v.z - mean) * inv * g.z + b.z, 0.f);
    o.w = fmaxf((v.w - mean) * inv * g.w + b.w, 0.f);
    *(float4*)(out + (size_t)row * FF + tid * 4) = o;
}

// ---------------------------------------------------------------------------
extern "C" void kernel_launch(void* const* d_in, const int* in_sizes, int n_in,
                              void* d_out, int out_size) {
    const float* x     = (const float*)d_in[0];
    const float* W1    = (const float*)d_in[1];
    const float* b1    = (const float*)d_in[2];
    const float* W2    = (const float*)d_in[3];
    const float* b2    = (const float*)d_in[4];
    const float* gamma = (const float*)d_in[5];
    const float* beta  = (const float*)d_in[6];
    float* out = (float*)d_out;

    rowsum_kernel<<<BT / 8, dim3(32, 8)>>>(x);
    gemm1_kernel<<<BT / 128, 256>>>(x, W1, b1);
    gemm2_kernel<<<dim3(FF / 128, BT / 128), 256>>>(x, W2, b2, out);
    ln_kernel<<<BT, 128>>>(out, gamma, beta);
}

// round 3
// speedup vs baseline: 1.5633x; 1.5633x over previous
#include <cuda_runtime.h>
#include <cuda_bf16.h>
#include <cstdint>

// Problem dims
#define BT 16384   // B*T = 8*2048
#define TSEQ 2048
#define DD 512
#define HH 128
#define NK 7
#define FF 512
#define KF 3584    // NK*FF
#define KDIM2 896  // NK*HH

// Scratch (allocation-free rule: __device__ globals)
__device__ float g_rs[BT];
__device__ float g_h[BT * HH];
__device__ __nv_bfloat16 g_Bhi[FF * KDIM2];   // W2T hi  [f][p], p=k*128+h
__device__ __nv_bfloat16 g_Blo[FF * KDIM2];   // W2T lo
__device__ __nv_bfloat16 g_W1hi[HH * DD];     // W1T hi  [h][d]
__device__ __nv_bfloat16 g_W1lo[HH * DD];     // W1T lo

// ---------------------------------------------------------------------------
// Helpers (base sm_103-safe: ldmatrix / mma.sync / cp.async only)
// ---------------------------------------------------------------------------
__device__ __forceinline__ uint32_t smem_u32(const void* p) {
    uint32_t a;
    asm("{ .reg .u64 t; cvta.to.shared.u64 t, %1; cvt.u32.u64 %0, t; }" : "=r"(a) : "l"(p));
    return a;
}
__device__ __forceinline__ void ldsm_x4(uint32_t a, uint32_t* r) {
    asm volatile("ldmatrix.sync.aligned.m8n8.x4.shared.b16 {%0,%1,%2,%3}, [%4];"
                 : "=r"(r[0]), "=r"(r[1]), "=r"(r[2]), "=r"(r[3]) : "r"(a));
}
__device__ __forceinline__ void mma16816(float* c, const uint32_t* a,
                                         uint32_t b0, uint32_t b1) {
    asm volatile("mma.sync.aligned.m16n8k16.row.col.f32.bf16.bf16.f32 "
                 "{%0,%1,%2,%3}, {%4,%5,%6,%7}, {%8,%9}, {%0,%1,%2,%3};"
                 : "+f"(c[0]), "+f"(c[1]), "+f"(c[2]), "+f"(c[3])
                 : "r"(a[0]), "r"(a[1]), "r"(a[2]), "r"(a[3]), "r"(b0), "r"(b1));
}
#define CP_ASYNC16(dst, src) \
    asm volatile("cp.async.cg.shared.global [%0], [%1], 16;" :: "r"(dst), "l"(src))
#define CP_COMMIT() asm volatile("cp.async.commit_group;" ::: "memory")
#define CP_WAIT0()  asm volatile("cp.async.wait_group 0;" ::: "memory")
#define SWZ(o) ((o) ^ (((o) >> 3) & 0x70))

// ---------------------------------------------------------------------------
// Kernel 1: per-token channel rowsum
// ---------------------------------------------------------------------------
__global__ void rowsum_kernel(const float* __restrict__ x) {
    int row = blockIdx.x * 8 + threadIdx.y;
    int lane = threadIdx.x;
    const float4* xr = (const float4*)(x + (size_t)row * DD);
    float s = 0.f;
#pragma unroll
    for (int j = lane; j < DD / 4; j += 32) {
        float4 v = xr[j];
        s += (v.x + v.y) + (v.z + v.w);
    }
#pragma unroll
    for (int o = 16; o; o >>= 1) s += __shfl_xor_sync(0xffffffffu, s, o);
    if (lane == 0) g_rs[row] = s;
}

// ---------------------------------------------------------------------------
// Prep: transpose + bf16 hi/lo split of W2 and W1
// ---------------------------------------------------------------------------
__global__ __launch_bounds__(256) void prep_w2_kernel(const float* __restrict__ W2) {
    int idx = blockIdx.x * 256 + threadIdx.x;  // f fastest: coalesced read
    int p = idx >> 9, f = idx & 511;
    int k = p >> 7, h = p & 127;
    float v = W2[(size_t)h * KF + k * FF + f];
    __nv_bfloat16 hi = __float2bfloat16(v);
    g_Bhi[(size_t)f * KDIM2 + p] = hi;
    g_Blo[(size_t)f * KDIM2 + p] = __float2bfloat16(v - __bfloat162float(hi));
}
__global__ __launch_bounds__(256) void prep_w1_kernel(const float* __restrict__ W1) {
    int idx = blockIdx.x * 256 + threadIdx.x;  // 65536
    int h = idx >> 9, d = idx & 511;
    float v = W1[(size_t)d * HH + h];
    __nv_bfloat16 hi = __float2bfloat16(v);
    g_W1hi[idx] = hi;
    g_W1lo[idx] = __float2bfloat16(v - __bfloat162float(hi));
}

// ---------------------------------------------------------------------------
// GEMM1: h = relu(x @ W1 + b1), warp-MMA bf16 hi/lo
// CTA: 128 rows x 128 cols(H), K=512 in 8 chunks of 64, double-buffered
// smem stage: Ah,Al,Bh,Bl each 128x64 bf16 (16KB) -> 64KB/stage
// ---------------------------------------------------------------------------
#define G1_STAGE 65536
#define G1_TOTAL 131072
__global__ __launch_bounds__(256, 1) void gemm1_mma_kernel(
    const float* __restrict__ x, const float* __restrict__ b1) {
    extern __shared__ char smem[];
    uint32_t sb = smem_u32(smem);
    int tid = threadIdx.x;
    int warp = tid >> 5, lane = tid & 31;
    int wm = warp & 1, wn = warp >> 1;
    int rowBase = blockIdx.x * 128;

    float acc[4][4][4];
#pragma unroll
    for (int a = 0; a < 4; a++)
#pragma unroll
        for (int b = 0; b < 4; b++)
#pragma unroll
            for (int cc = 0; cc < 4; cc++) acc[a][b][cc] = 0.f;

    auto build = [&](int c, int s) {
        char* ah = smem + s * G1_STAGE;
        char* al = ah + 16384;
        int p0 = c * 64;
        // A: x rows, cols p0..p0+63, hi/lo split
#pragma unroll
        for (int i = 0; i < 8; i++) {
            int lin = i * 256 + tid;
            int row = lin >> 4, c4 = lin & 15;
            float4 v = *(const float4*)(x + (size_t)(rowBase + row) * DD + p0 + c4 * 4);
            __nv_bfloat16 q0 = __float2bfloat16(v.x), q1 = __float2bfloat16(v.y);
            __nv_bfloat16 q2 = __float2bfloat16(v.z), q3 = __float2bfloat16(v.w);
            __nv_bfloat162 hp0(q0, q1), hp1(q2, q3);
            __nv_bfloat162 lp0(__float2bfloat16(v.x - __bfloat162float(q0)),
                               __float2bfloat16(v.y - __bfloat162float(q1)));
            __nv_bfloat162 lp1(__float2bfloat16(v.z - __bfloat162float(q2)),
                               __float2bfloat16(v.w - __bfloat162float(q3)));
            uint2 wh, wl;
            wh.x = *(uint32_t*)&hp0; wh.y = *(uint32_t*)&hp1;
            wl.x = *(uint32_t*)&lp0; wl.y = *(uint32_t*)&lp1;
            uint32_t sw = SWZ(row * 128 + c4 * 8);
            *(uint2*)(ah + sw) = wh;
            *(uint2*)(al + sw) = wl;
        }
        // B: W1T rows h=0..127, cols d chunk, via cp.async
        uint32_t bh_s = sb + s * G1_STAGE + 32768;
        uint32_t bl_s = bh_s + 16384;
#pragma unroll
        for (int i = 0; i < 4; i++) {
            int lin = i * 256 + tid;
            int row = lin >> 3, c16 = lin & 7;
            uint32_t sw = SWZ(row * 128 + c16 * 16);
            size_t src = (size_t)row * DD + p0 + c16 * 8;
            CP_ASYNC16(bh_s + sw, g_W1hi + src);
            CP_ASYNC16(bl_s + sw, g_W1lo + src);
        }
        CP_COMMIT();
    };

    build(0, 0);
    for (int c = 0; c < 8; c++) {
        int s = c & 1;
        CP_WAIT0();
        __syncthreads();
        if (c < 7) build(c + 1, s ^ 1);
        uint32_t ah_s = sb + s * G1_STAGE;
        uint32_t al_s = ah_s + 16384;
        uint32_t bh_s = ah_s + 32768;
        uint32_t bl_s = ah_s + 49152;
        int r = lane & 15, half = lane >> 4;
#pragma unroll
        for (int k16 = 0; k16 < 4; k16++) {
            int kc = k16 * 32 + half * 16;
            uint32_t ah[4][4], al[4][4], bh[2][4], bl[2][4];
#pragma unroll
            for (int mt = 0; mt < 4; mt++) {
                uint32_t o = SWZ((wm * 64 + mt * 16 + r) * 128 + kc);
                ldsm_x4(ah_s + o, ah[mt]);
                ldsm_x4(al_s + o, al[mt]);
            }
#pragma unroll
            for (int g = 0; g < 2; g++) {
                uint32_t o = SWZ((wn * 32 + g * 16 + r) * 128 + kc);
                ldsm_x4(bh_s + o, bh[g]);
                ldsm_x4(bl_s + o, bl[g]);
            }
#pragma unroll
            for (int mt = 0; mt < 4; mt++)
#pragma unroll
                for (int nt = 0; nt < 4; nt++) {
                    int g = nt >> 1, i2 = nt & 1;
                    mma16816(acc[mt][nt], ah[mt], bh[g][i2], bh[g][i2 + 2]);
                    mma16816(acc[mt][nt], ah[mt], bl[g][i2], bl[g][i2 + 2]);
                    mma16816(acc[mt][nt], al[mt], bh[g][i2], bh[g][i2 + 2]);
                }
        }
    }

    // epilogue: relu(acc + b1) -> g_h
    int r = lane >> 2, cp2 = (lane & 3) * 2;
#pragma unroll
    for (int mt = 0; mt < 4; mt++) {
        int row0 = wm * 64 + mt * 16 + r;
        float* o0 = g_h + (size_t)(rowBase + row0) * HH;
        float* o1 = o0 + 8 * HH;
#pragma unroll
        for (int nt = 0; nt < 4; nt++) {
            int col = wn * 32 + nt * 8 + cp2;
            float2 bb = *(const float2*)(b1 + col);
            float2 v0, v1;
            v0.x = fmaxf(acc[mt][nt][0] + bb.x, 0.f);
            v0.y = fmaxf(acc[mt][nt][1] + bb.y, 0.f);
            v1.x = fmaxf(acc[mt][nt][2] + bb.x, 0.f);
            v1.y = fmaxf(acc[mt][nt][3] + bb.y, 0.f);
            *(float2*)(o0 + col) = v0;
            *(float2*)(o1 + col) = v1;
        }
    }
}

// ---------------------------------------------------------------------------
// GEMM2: dynamic conv as GEMM on warp-MMA bf16 hi/lo
// out[t,f] = x[t,f] + sum_p A[t,p]*W2T[f,p] + sum_k rs[t+k]*b2[k*F+f]
//   A[t, k*128+h] = rs_window * h[t,h]  (built on the fly, hi/lo split)
// CTA: 128 rows x 128 f, K=896 in 14 chunks of 64, double-buffered
// ---------------------------------------------------------------------------
#define SM_RS 0
#define SM_B2 1024
#define SM_TILES 8192
#define G2_STAGE 65536
#define G2_TOTAL (SM_TILES + 2 * G2_STAGE)
__global__ __launch_bounds__(256, 1) void gemm2_mma_kernel(
    const float* __restrict__ x, const float* __restrict__ b2,
    float* __restrict__ out) {
    extern __shared__ char smem[];
    uint32_t sb = smem_u32(smem);
    int tid = threadIdx.x;
    int warp = tid >> 5, lane = tid & 31;
    int wm = warp & 1, wn = warp >> 1;
    int rowBase = blockIdx.y * 128;
    int fBase = blockIdx.x * 128;

    float* rs_s = (float*)(smem + SM_RS);
    float* b2_s = (float*)(smem + SM_B2);
    int bstart = (rowBase / TSEQ) * TSEQ;
    if (tid < 136) {
        int gi = rowBase + tid - 3;
        float v = 0.f;
        if (tid < 134 && gi >= bstart && gi < bstart + TSEQ) v = g_rs[gi];
        rs_s[tid] = v;
    }
    for (int i = tid; i < NK * 128; i += 256)
        b2_s[i] = b2[(i >> 7) * FF + fBase + (i & 127)];
    __syncthreads();

    const size_t hrow = (size_t)rowBase * HH;
    const size_t brow = (size_t)fBase * KDIM2;

    float acc[4][4][4];
#pragma unroll
    for (int a = 0; a < 4; a++)
#pragma unroll
        for (int b = 0; b < 4; b++)
#pragma unroll
            for (int cc = 0; cc < 4; cc++) acc[a][b][cc] = 0.f;

    auto build = [&](int c, int s) {
        char* ah = smem + SM_TILES + s * G2_STAGE;
        char* al = ah + 16384;
        int ktap = c >> 1;
        int h0 = (c & 1) * 64;
        int p0 = c * 64;
        // A: rs-scaled g_h, hi/lo split
#pragma unroll
        for (int i = 0; i < 8; i++) {
            int lin = i * 256 + tid;
            int row = lin >> 4, c4 = lin & 15;
            float4 v = *(const float4*)(g_h + hrow + (size_t)row * HH + h0 + c4 * 4);
            float sc = rs_s[row + ktap];
            float a0 = v.x * sc, a1 = v.y * sc, a2 = v.z * sc, a3 = v.w * sc;
            __nv_bfloat16 q0 = __float2bfloat16(a0), q1 = __float2bfloat16(a1);
            __nv_bfloat16 q2 = __float2bfloat16(a2), q3 = __float2bfloat16(a3);
            __nv_bfloat162 hp0(q0, q1), hp1(q2, q3);
            __nv_bfloat162 lp0(__float2bfloat16(a0 - __bfloat162float(q0)),
                               __float2bfloat16(a1 - __bfloat162float(q1)));
            __nv_bfloat162 lp1(__float2bfloat16(a2 - __bfloat162float(q2)),
                               __float2bfloat16(a3 - __bfloat162float(q3)));
            uint2 wh, wl;
            wh.x = *(uint32_t*)&hp0; wh.y = *(uint32_t*)&hp1;
            wl.x = *(uint32_t*)&lp0; wl.y = *(uint32_t*)&lp1;
            uint32_t sw = SWZ(row * 128 + c4 * 8);
            *(uint2*)(ah + sw) = wh;
            *(uint2*)(al + sw) = wl;
        }
        // B: W2T hi/lo rows f, cols p chunk, via cp.async
        uint32_t bh_s = sb + SM_TILES + s * G2_STAGE + 32768;
        uint32_t bl_s = bh_s + 16384;
#pragma unroll
        for (int i = 0; i < 4; i++) {
            int lin = i * 256 + tid;
            int row = lin >> 3, c16 = lin & 7;
            uint32_t sw = SWZ(row * 128 + c16 * 16);
            size_t src = brow + (size_t)row * KDIM2 + p0 + c16 * 8;
            CP_ASYNC16(bh_s + sw, g_Bhi + src);
            CP_ASYNC16(bl_s + sw, g_Blo + src);
        }
        CP_COMMIT();
    };

    build(0, 0);
    for (int c = 0; c < 14; c++) {
        int s = c & 1;
        CP_WAIT0();
        __syncthreads();
        if (c < 13) build(c + 1, s ^ 1);
        uint32_t ah_s = sb + SM_TILES + s * G2_STAGE;
        uint32_t al_s = ah_s + 16384;
        uint32_t bh_s = ah_s + 32768;
        uint32_t bl_s = ah_s + 49152;
        int r = lane & 15, half = lane >> 4;
#pragma unroll
        for (int k16 = 0; k16 < 4; k16++) {
            int kc = k16 * 32 + half * 16;
            uint32_t ah[4][4], al[4][4], bh[2][4], bl[2][4];
#pragma unroll
            for (int mt = 0; mt < 4; mt++) {
                uint32_t o = SWZ((wm * 64 + mt * 16 + r) * 128 + kc);
                ldsm_x4(ah_s + o, ah[mt]);
                ldsm_x4(al_s + o, al[mt]);
            }
#pragma unroll
            for (int g = 0; g < 2; g++) {
                uint32_t o = SWZ((wn * 32 + g * 16 + r) * 128 + kc);
                ldsm_x4(bh_s + o, bh[g]);
                ldsm_x4(bl_s + o, bl[g]);
            }
#pragma unroll
            for (int mt = 0; mt < 4; mt++)
#pragma unroll
                for (int nt = 0; nt < 4; nt++) {
                    int g = nt >> 1, i2 = nt & 1;
                    mma16816(acc[mt][nt], ah[mt], bh[g][i2], bh[g][i2 + 2]);
                    mma16816(acc[mt][nt], ah[mt], bl[g][i2], bl[g][i2 + 2]);
                    mma16816(acc[mt][nt], al[mt], bh[g][i2], bh[g][i2 + 2]);
                }
        }
    }

    // epilogue: + rs-window bias + residual, write pre-LN y
    int r = lane >> 2, cp2 = (lane & 3) * 2;
#pragma unroll
    for (int mt = 0; mt < 4; mt++) {
        int row0 = wm * 64 + mt * 16 + r;
        int row1 = row0 + 8;
        float rv0[NK], rv1[NK];
#pragma unroll
        for (int k = 0; k < NK; k++) { rv0[k] = rs_s[row0 + k]; rv1[k] = rs_s[row1 + k]; }
        const float* x0 = x + (size_t)(rowBase + row0) * DD + fBase;
        const float* x1 = x0 + 8 * DD;
        float* o0 = out + (size_t)(rowBase + row0) * FF + fBase;
        float* o1 = o0 + 8 * FF;
#pragma unroll
        for (int nt = 0; nt < 4; nt++) {
            int col = wn * 32 + nt * 8 + cp2;
            float b00 = 0.f, b01 = 0.f, b10 = 0.f, b11 = 0.f;
#pragma unroll
            for (int k = 0; k < NK; k++) {
                float2 bb = *(const float2*)&b2_s[k * 128 + col];
                b00 = fmaf(rv0[k], bb.x, b00);
                b01 = fmaf(rv0[k], bb.y, b01);
                b10 = fmaf(rv1[k], bb.x, b10);
                b11 = fmaf(rv1[k], bb.y, b11);
            }
            float2 xv0 = *(const float2*)(x0 + col);
            float2 xv1 = *(const float2*)(x1 + col);
            float2 v0, v1;
            v0.x = acc[mt][nt][0] + xv0.x + b00;
            v0.y = acc[mt][nt][1] + xv0.y + b01;
            v1.x = acc[mt][nt][2] + xv1.x + b10;
            v1.y = acc[mt][nt][3] + xv1.y + b11;
            *(float2*)(o0 + col) = v0;
            *(float2*)(o1 + col) = v1;
        }
    }
}

// ---------------------------------------------------------------------------
// Kernel 4: in-place LayerNorm(eps=1e-3) + relu
// ---------------------------------------------------------------------------
__global__ __launch_bounds__(128) void ln_kernel(
    float* __restrict__ out, const float* __restrict__ gamma,
    const float* __restrict__ beta) {
    int row = blockIdx.x;
    int tid = threadIdx.x;
    float4 v = *(const float4*)(out + (size_t)row * FF + tid * 4);
    float s = (v.x + v.y) + (v.z + v.w);
    float s2 = (v.x * v.x + v.y * v.y) + (v.z * v.z + v.w * v.w);
#pragma unroll
    for (int o = 16; o; o >>= 1) {
        s += __shfl_xor_sync(0xffffffffu, s, o);
        s2 += __shfl_xor_sync(0xffffffffu, s2, o);
    }
    __shared__ float sred[8];
    int w = tid >> 5;
    if ((tid & 31) == 0) { sred[w] = s; sred[4 + w] = s2; }
    __syncthreads();
    s = (sred[0] + sred[1]) + (sred[2] + sred[3]);
    s2 = (sred[4] + sred[5]) + (sred[6] + sred[7]);
    float mean = s * (1.f / FF);
    float var = s2 * (1.f / FF) - mean * mean;
    float inv = rsqrtf(var + 1e-3f);
    float4 g = *(const float4*)(gamma + tid * 4);
    float4 b = *(const float4*)(beta + tid * 4);
    float4 o;
    o.x = fmaxf((v.x - mean) * inv * g.x + b.x, 0.f);
    o.y = fmaxf((v.y - mean) * inv * g.y + b.y, 0.f);
    o.z = fmaxf((v.z - mean) * inv * g.z + b.z, 0.f);
    o.w = fmaxf((v.w - mean) * inv * g.w + b.w, 0.f);
    *(float4*)(out + (size_t)row * FF + tid * 4) = o;
}

// ---------------------------------------------------------------------------
extern "C" void kernel_launch(void* const* d_in, const int* in_sizes, int n_in,
                              void* d_out, int out_size) {
    const float* x     = (const float*)d_in[0];
    const float* W1    = (const float*)d_in[1];
    const float* b1    = (const float*)d_in[2];
    const float* W2    = (const float*)d_in[3];
    const float* b2    = (const float*)d_in[4];
    const float* gamma = (const float*)d_in[5];
    const float* beta  = (const float*)d_in[6];
    float* out = (float*)d_out;

    cudaFuncSetAttribute(gemm1_mma_kernel,
                         cudaFuncAttributeMaxDynamicSharedMemorySize, G1_TOTAL);
    cudaFuncSetAttribute(gemm2_mma_kernel,
                         cudaFuncAttributeMaxDynamicSharedMemorySize, G2_TOTAL);

    rowsum_kernel<<<BT / 8, dim3(32, 8)>>>(x);
    prep_w1_kernel<<<(HH * DD) / 256, 256>>>(W1);
    prep_w2_kernel<<<(FF * KDIM2) / 256, 256>>>(W2);
    gemm1_mma_kernel<<<BT / 128, 256, G1_TOTAL>>>(x, b1);
    gemm2_mma_kernel<<<dim3(FF / 128, BT / 128), 256, G2_TOTAL>>>(x, b2, out);
    ln_kernel<<<BT, 128>>>(out, gamma, beta);
}

// round 4
// speedup vs baseline: 2.4970x; 1.5972x over previous
#include <cuda_runtime.h>
#include <cuda_bf16.h>
#include <cstdint>

// Problem dims
#define BT 16384   // B*T = 8*2048
#define TSEQ 2048
#define DD 512
#define HH 128
#define NK 7
#define FF 512
#define KF 3584    // NK*FF
#define KDIM2 896  // NK*HH

// Scratch (allocation-free rule: __device__ globals)
__device__ float g_rs[BT];
__device__ float g_h[BT * HH];
__device__ __nv_bfloat16 g_Bhi[FF * KDIM2];   // W2T hi  [f][p], p=k*128+h
__device__ __nv_bfloat16 g_Blo[FF * KDIM2];   // W2T lo
__device__ __nv_bfloat16 g_W1hi[HH * DD];     // W1T hi  [h][d]
__device__ __nv_bfloat16 g_W1lo[HH * DD];     // W1T lo

// ---------------------------------------------------------------------------
// Helpers (base sm_103-safe: ldmatrix / mma.sync / cp.async only)
// ---------------------------------------------------------------------------
__device__ __forceinline__ uint32_t smem_u32(const void* p) {
    uint32_t a;
    asm("{ .reg .u64 t; cvta.to.shared.u64 t, %1; cvt.u32.u64 %0, t; }" : "=r"(a) : "l"(p));
    return a;
}
__device__ __forceinline__ void ldsm_x4(uint32_t a, uint32_t* r) {
    asm volatile("ldmatrix.sync.aligned.m8n8.x4.shared.b16 {%0,%1,%2,%3}, [%4];"
                 : "=r"(r[0]), "=r"(r[1]), "=r"(r[2]), "=r"(r[3]) : "r"(a));
}
__device__ __forceinline__ void mma16816(float* c, const uint32_t* a,
                                         uint32_t b0, uint32_t b1) {
    asm volatile("mma.sync.aligned.m16n8k16.row.col.f32.bf16.bf16.f32 "
                 "{%0,%1,%2,%3}, {%4,%5,%6,%7}, {%8,%9}, {%0,%1,%2,%3};"
                 : "+f"(c[0]), "+f"(c[1]), "+f"(c[2]), "+f"(c[3])
                 : "r"(a[0]), "r"(a[1]), "r"(a[2]), "r"(a[3]), "r"(b0), "r"(b1));
}
#define CP_ASYNC16(dst, src) \
    asm volatile("cp.async.cg.shared.global [%0], [%1], 16;" :: "r"(dst), "l"(src))
#define CP_COMMIT() asm volatile("cp.async.commit_group;" ::: "memory")
#define CP_WAIT0()  asm volatile("cp.async.wait_group 0;" ::: "memory")
#define SWZ(o) ((o) ^ (((o) >> 3) & 0x70))

// split fp32x4 -> bf16 hi/lo packed pairs
__device__ __forceinline__ void split4(float a0, float a1, float a2, float a3,
                                       uint2& wh, uint2& wl) {
    __nv_bfloat16 q0 = __float2bfloat16(a0), q1 = __float2bfloat16(a1);
    __nv_bfloat16 q2 = __float2bfloat16(a2), q3 = __float2bfloat16(a3);
    __nv_bfloat162 hp0(q0, q1), hp1(q2, q3);
    __nv_bfloat162 lp0(__float2bfloat16(a0 - __bfloat162float(q0)),
                       __float2bfloat16(a1 - __bfloat162float(q1)));
    __nv_bfloat162 lp1(__float2bfloat16(a2 - __bfloat162float(q2)),
                       __float2bfloat16(a3 - __bfloat162float(q3)));
    wh.x = *(uint32_t*)&hp0; wh.y = *(uint32_t*)&hp1;
    wl.x = *(uint32_t*)&lp0; wl.y = *(uint32_t*)&lp1;
}

// ---------------------------------------------------------------------------
// Kernel 1: per-token channel rowsum
// ---------------------------------------------------------------------------
__global__ void rowsum_kernel(const float* __restrict__ x) {
    int row = blockIdx.x * 8 + threadIdx.y;
    int lane = threadIdx.x;
    const float4* xr = (const float4*)(x + (size_t)row * DD);
    float s = 0.f;
#pragma unroll
    for (int j = lane; j < DD / 4; j += 32) {
        float4 v = xr[j];
        s += (v.x + v.y) + (v.z + v.w);
    }
#pragma unroll
    for (int o = 16; o; o >>= 1) s += __shfl_xor_sync(0xffffffffu, s, o);
    if (lane == 0) g_rs[row] = s;
}

// ---------------------------------------------------------------------------
// Prep: transpose + bf16 hi/lo split of W2 and W1
// ---------------------------------------------------------------------------
__global__ __launch_bounds__(256) void prep_w2_kernel(const float* __restrict__ W2) {
    int idx = blockIdx.x * 256 + threadIdx.x;  // f fastest: coalesced read
    int p = idx >> 9, f = idx & 511;
    int k = p >> 7, h = p & 127;
    float v = W2[(size_t)h * KF + k * FF + f];
    __nv_bfloat16 hi = __float2bfloat16(v);
    g_Bhi[(size_t)f * KDIM2 + p] = hi;
    g_Blo[(size_t)f * KDIM2 + p] = __float2bfloat16(v - __bfloat162float(hi));
}
__global__ __launch_bounds__(256) void prep_w1_kernel(const float* __restrict__ W1) {
    int idx = blockIdx.x * 256 + threadIdx.x;  // 65536
    int h = idx >> 9, d = idx & 511;
    float v = W1[(size_t)d * HH + h];
    __nv_bfloat16 hi = __float2bfloat16(v);
    g_W1hi[idx] = hi;
    g_W1lo[idx] = __float2bfloat16(v - __bfloat162float(hi));
}

// ---------------------------------------------------------------------------
// GEMM1: h = relu(x @ W1 + b1), warp-MMA bf16 hi/lo
// CTA: 64 rows x 128 cols(H), 256 thr, 8 warps (2M x 4N), warp tile 32x32
// K=512 in 8 chunks of 64, double-buffered; stage=48KB
// ---------------------------------------------------------------------------
#define G1_STAGE 49152
#define G1_TOTAL 98304
__global__ __launch_bounds__(256, 2) void gemm1_mma_kernel(
    const float* __restrict__ x, const float* __restrict__ b1) {
    extern __shared__ char smem[];
    uint32_t sb = smem_u32(smem);
    int tid = threadIdx.x;
    int warp = tid >> 5, lane = tid & 31;
    int wm = warp & 1, wn = warp >> 1;   // wm: 0..1 (32 rows), wn: 0..3 (32 cols)
    int rowBase = blockIdx.x * 64;

    float acc[2][4][4];
#pragma unroll
    for (int a = 0; a < 2; a++)
#pragma unroll
        for (int b = 0; b < 4; b++)
#pragma unroll
            for (int cc = 0; cc < 4; cc++) acc[a][b][cc] = 0.f;

    auto build = [&](int c, int s) {
        char* ah = smem + s * G1_STAGE;           // 64x64 bf16 = 8KB
        char* al = ah + 8192;
        int p0 = c * 64;
        // A: x rows, 64x16 float4 = 1024 units / 256 thr = 4 iters
#pragma unroll
        for (int i = 0; i < 4; i++) {
            int lin = i * 256 + tid;
            int row = lin >> 4, c4 = lin & 15;
            float4 v = *(const float4*)(x + (size_t)(rowBase + row) * DD + p0 + c4 * 4);
            uint2 wh, wl;
            split4(v.x, v.y, v.z, v.w, wh, wl);
            uint32_t sw = SWZ(row * 128 + c4 * 8);
            *(uint2*)(ah + sw) = wh;
            *(uint2*)(al + sw) = wl;
        }
        // B: W1T 128x64 bf16 via cp.async
        uint32_t bh_s = sb + s * G1_STAGE + 16384;
        uint32_t bl_s = bh_s + 16384;
#pragma unroll
        for (int i = 0; i < 4; i++) {
            int lin = i * 256 + tid;
            int row = lin >> 3, c16 = lin & 7;
            uint32_t sw = SWZ(row * 128 + c16 * 16);
            size_t src = (size_t)row * DD + p0 + c16 * 8;
            CP_ASYNC16(bh_s + sw, g_W1hi + src);
            CP_ASYNC16(bl_s + sw, g_W1lo + src);
        }
        CP_COMMIT();
    };

    build(0, 0);
    for (int c = 0; c < 8; c++) {
        int s = c & 1;
        CP_WAIT0();
        __syncthreads();
        if (c < 7) build(c + 1, s ^ 1);
        uint32_t ah_s = sb + s * G1_STAGE;
        uint32_t al_s = ah_s + 8192;
        uint32_t bh_s = ah_s + 16384;
        uint32_t bl_s = ah_s + 32768;
        int r = lane & 15, half = lane >> 4;
#pragma unroll
        for (int k16 = 0; k16 < 4; k16++) {
            int kc = k16 * 32 + half * 16;
            uint32_t ah[2][4], al[2][4], bh[2][4], bl[2][4];
#pragma unroll
            for (int mt = 0; mt < 2; mt++) {
                uint32_t o = SWZ((wm * 32 + mt * 16 + r) * 128 + kc);
                ldsm_x4(ah_s + o, ah[mt]);
                ldsm_x4(al_s + o, al[mt]);
            }
#pragma unroll
            for (int g = 0; g < 2; g++) {
                uint32_t o = SWZ((wn * 32 + g * 16 + r) * 128 + kc);
                ldsm_x4(bh_s + o, bh[g]);
                ldsm_x4(bl_s + o, bl[g]);
            }
#pragma unroll
            for (int mt = 0; mt < 2; mt++)
#pragma unroll
                for (int nt = 0; nt < 4; nt++) {
                    int g = nt >> 1, i2 = nt & 1;
                    mma16816(acc[mt][nt], ah[mt], bh[g][i2], bh[g][i2 + 2]);
                    mma16816(acc[mt][nt], ah[mt], bl[g][i2], bl[g][i2 + 2]);
                    mma16816(acc[mt][nt], al[mt], bh[g][i2], bh[g][i2 + 2]);
                }
        }
    }

    // epilogue: relu(acc + b1) -> g_h
    int r = lane >> 2, cp2 = (lane & 3) * 2;
#pragma unroll
    for (int mt = 0; mt < 2; mt++) {
        int row0 = wm * 32 + mt * 16 + r;
        float* o0 = g_h + (size_t)(rowBase + row0) * HH;
        float* o1 = o0 + 8 * HH;
#pragma unroll
        for (int nt = 0; nt < 4; nt++) {
            int col = wn * 32 + nt * 8 + cp2;
            float2 bb = *(const float2*)(b1 + col);
            float2 v0, v1;
            v0.x = fmaxf(acc[mt][nt][0] + bb.x, 0.f);
            v0.y = fmaxf(acc[mt][nt][1] + bb.y, 0.f);
            v1.x = fmaxf(acc[mt][nt][2] + bb.x, 0.f);
            v1.y = fmaxf(acc[mt][nt][3] + bb.y, 0.f);
            *(float2*)(o0 + col) = v0;
            *(float2*)(o1 + col) = v1;
        }
    }
}

// ---------------------------------------------------------------------------
// GEMM2: dynamic conv as GEMM, warp-MMA bf16 hi/lo
// CTA: 128 rows x 256 f, 512 thr, 16 warps (4M x 4N), warp tile 32x64
// K=896 in 14 chunks of 64, double-buffered; stage=96KB
// ---------------------------------------------------------------------------
#define SM_RS 0
#define SM_B2 1024          // 7*256 floats = 7168 B
#define SM_TILES 8192
#define G2_STAGE 98304
#define G2_TOTAL (SM_TILES + 2 * G2_STAGE)   // 204800
__global__ __launch_bounds__(512, 1) void gemm2_mma_kernel(
    const float* __restrict__ x, const float* __restrict__ b2,
    float* __restrict__ out) {
    extern __shared__ char smem[];
    uint32_t sb = smem_u32(smem);
    int tid = threadIdx.x;
    int warp = tid >> 5, lane = tid & 31;
    int wm = warp & 3, wn = warp >> 2;    // wm: 0..3 (32 rows), wn: 0..3 (64 cols)
    int rowBase = blockIdx.y * 128;
    int fBase = blockIdx.x * 256;

    float* rs_s = (float*)(smem + SM_RS);
    float* b2_s = (float*)(smem + SM_B2);
    int bstart = (rowBase / TSEQ) * TSEQ;
    if (tid < 136) {
        int gi = rowBase + tid - 3;
        float v = 0.f;
        if (tid < 134 && gi >= bstart && gi < bstart + TSEQ) v = g_rs[gi];
        rs_s[tid] = v;
    }
    for (int i = tid; i < NK * 256; i += 512)
        b2_s[i] = b2[(i >> 8) * FF + fBase + (i & 255)];
    __syncthreads();

    const size_t hrow = (size_t)rowBase * HH;
    const size_t brow = (size_t)fBase * KDIM2;

    float acc[2][8][4];
#pragma unroll
    for (int a = 0; a < 2; a++)
#pragma unroll
        for (int b = 0; b < 8; b++)
#pragma unroll
            for (int cc = 0; cc < 4; cc++) acc[a][b][cc] = 0.f;

    auto build = [&](int c, int s) {
        char* ah = smem + SM_TILES + s * G2_STAGE;   // 128x64 bf16 = 16KB
        char* al = ah + 16384;
        int ktap = c >> 1;
        int h0 = (c & 1) * 64;
        int p0 = c * 64;
        // A: rs-scaled g_h, 128x16 float4 = 2048 units / 512 thr = 4 iters
#pragma unroll
        for (int i = 0; i < 4; i++) {
            int lin = i * 512 + tid;
            int row = lin >> 4, c4 = lin & 15;
            float4 v = *(const float4*)(g_h + hrow + (size_t)row * HH + h0 + c4 * 4);
            float sc = rs_s[row + ktap];
            uint2 wh, wl;
            split4(v.x * sc, v.y * sc, v.z * sc, v.w * sc, wh, wl);
            uint32_t sw = SWZ(row * 128 + c4 * 8);
            *(uint2*)(ah + sw) = wh;
            *(uint2*)(al + sw) = wl;
        }
        // B: W2T 256x64 bf16 hi/lo via cp.async: 2048 chunks / 512 = 4 iters
        uint32_t bh_s = sb + SM_TILES + s * G2_STAGE + 32768;
        uint32_t bl_s = bh_s + 32768;
#pragma unroll
        for (int i = 0; i < 4; i++) {
            int lin = i * 512 + tid;
            int row = lin >> 3, c16 = lin & 7;
            uint32_t sw = SWZ(row * 128 + c16 * 16);
            size_t src = brow + (size_t)row * KDIM2 + p0 + c16 * 8;
            CP_ASYNC16(bh_s + sw, g_Bhi + src);
            CP_ASYNC16(bl_s + sw, g_Blo + src);
        }
        CP_COMMIT();
    };

    build(0, 0);
    for (int c = 0; c < 14; c++) {
        int s = c & 1;
        CP_WAIT0();
        __syncthreads();
        if (c < 13) build(c + 1, s ^ 1);
        uint32_t ah_s = sb + SM_TILES + s * G2_STAGE;
        uint32_t al_s = ah_s + 16384;
        uint32_t bh_s = ah_s + 32768;
        uint32_t bl_s = ah_s + 65536;
        int r = lane & 15, half = lane >> 4;
#pragma unroll
        for (int k16 = 0; k16 < 4; k16++) {
            int kc = k16 * 32 + half * 16;
            uint32_t ah[2][4], al[2][4], bh[4][4], bl[4][4];
#pragma unroll
            for (int mt = 0; mt < 2; mt++) {
                uint32_t o = SWZ((wm * 32 + mt * 16 + r) * 128 + kc);
                ldsm_x4(ah_s + o, ah[mt]);
                ldsm_x4(al_s + o, al[mt]);
            }
#pragma unroll
            for (int g = 0; g < 4; g++) {
                uint32_t o = SWZ((wn * 64 + g * 16 + r) * 128 + kc);
                ldsm_x4(bh_s + o, bh[g]);
                ldsm_x4(bl_s + o, bl[g]);
            }
#pragma unroll
            for (int mt = 0; mt < 2; mt++)
#pragma unroll
                for (int nt = 0; nt < 8; nt++) {
                    int g = nt >> 1, i2 = nt & 1;
                    mma16816(acc[mt][nt], ah[mt], bh[g][i2], bh[g][i2 + 2]);
                    mma16816(acc[mt][nt], ah[mt], bl[g][i2], bl[g][i2 + 2]);
                    mma16816(acc[mt][nt], al[mt], bh[g][i2], bh[g][i2 + 2]);
                }
        }
    }

    // epilogue: + rs-window bias + residual, write pre-LN y
    int r = lane >> 2, cp2 = (lane & 3) * 2;
#pragma unroll
    for (int mt = 0; mt < 2; mt++) {
        int row0 = wm * 32 + mt * 16 + r;
        int row1 = row0 + 8;
        float rv0[NK], rv1[NK];
#pragma unroll
        for (int k = 0; k < NK; k++) { rv0[k] = rs_s[row0 + k]; rv1[k] = rs_s[row1 + k]; }
        const float* x0 = x + (size_t)(rowBase + row0) * DD + fBase;
        const float* x1 = x0 + 8 * DD;
        float* o0 = out + (size_t)(rowBase + row0) * FF + fBase;
        float* o1 = o0 + 8 * FF;
#pragma unroll
        for (int nt = 0; nt < 8; nt++) {
            int col = wn * 64 + nt * 8 + cp2;
            float b00 = 0.f, b01 = 0.f, b10 = 0.f, b11 = 0.f;
#pragma unroll
            for (int k = 0; k < NK; k++) {
                float2 bb = *(const float2*)&b2_s[k * 256 + col];
                b00 = fmaf(rv0[k], bb.x, b00);
                b01 = fmaf(rv0[k], bb.y, b01);
                b10 = fmaf(rv1[k], bb.x, b10);
                b11 = fmaf(rv1[k], bb.y, b11);
            }
            float2 xv0 = *(const float2*)(x0 + col);
            float2 xv1 = *(const float2*)(x1 + col);
            float2 v0, v1;
            v0.x = acc[mt][nt][0] + xv0.x + b00;
            v0.y = acc[mt][nt][1] + xv0.y + b01;
            v1.x = acc[mt][nt][2] + xv1.x + b10;
            v1.y = acc[mt][nt][3] + xv1.y + b11;
            *(float2*)(o0 + col) = v0;
            *(float2*)(o1 + col) = v1;
        }
    }
}

// ---------------------------------------------------------------------------
// Kernel 4: in-place LayerNorm(eps=1e-3) + relu
// ---------------------------------------------------------------------------
__global__ __launch_bounds__(128) void ln_kernel(
    float* __restrict__ out, const float* __restrict__ gamma,
    const float* __restrict__ beta) {
    int row = blockIdx.x;
    int tid = threadIdx.x;
    float4 v = *(const float4*)(out + (size_t)row * FF + tid * 4);
    float s = (v.x + v.y) + (v.z + v.w);
    float s2 = (v.x * v.x + v.y * v.y) + (v.z * v.z + v.w * v.w);
#pragma unroll
    for (int o = 16; o; o >>= 1) {
        s += __shfl_xor_sync(0xffffffffu, s, o);
        s2 += __shfl_xor_sync(0xffffffffu, s2, o);
    }
    __shared__ float sred[8];
    int w = tid >> 5;
    if ((tid & 31) == 0) { sred[w] = s; sred[4 + w] = s2; }
    __syncthreads();
    s = (sred[0] + sred[1]) + (sred[2] + sred[3]);
    s2 = (sred[4] + sred[5]) + (sred[6] + sred[7]);
    float mean = s * (1.f / FF);
    float var = s2 * (1.f / FF) - mean * mean;
    float inv = rsqrtf(var + 1e-3f);
    float4 g = *(const float4*)(gamma + tid * 4);
    float4 b = *(const float4*)(beta + tid * 4);
    float4 o;
    o.x = fmaxf((v.x - mean) * inv * g.x + b.x, 0.f);
    o.y = fmaxf((v.y - mean) * inv * g.y + b.y, 0.f);
    o.z = fmaxf((v.z - mean) * inv * g.z + b.z, 0.f);
    o.w = fmaxf((v.w - mean) * inv * g.w + b.w, 0.f);
    *(float4*)(out + (size_t)row * FF + tid * 4) = o;
}

// ---------------------------------------------------------------------------
extern "C" void kernel_launch(void* const* d_in, const int* in_sizes, int n_in,
                              void* d_out, int out_size) {
    const float* x     = (const float*)d_in[0];
    const float* W1    = (const float*)d_in[1];
    const float* b1    = (const float*)d_in[2];
    const float* W2    = (const float*)d_in[3];
    const float* b2    = (const float*)d_in[4];
    const float* gamma = (const float*)d_in[5];
    const float* beta  = (const float*)d_in[6];
    float* out = (float*)d_out;

    cudaFuncSetAttribute(gemm1_mma_kernel,
                         cudaFuncAttributeMaxDynamicSharedMemorySize, G1_TOTAL);
    cudaFuncSetAttribute(gemm2_mma_kernel,
                         cudaFuncAttributeMaxDynamicSharedMemorySize, G2_TOTAL);

    rowsum_kernel<<<BT / 8, dim3(32, 8)>>>(x);
    prep_w1_kernel<<<(HH * DD) / 256, 256>>>(W1);
    prep_w2_kernel<<<(FF * KDIM2) / 256, 256>>>(W2);
    gemm1_mma_kernel<<<BT / 64, 256, G1_TOTAL>>>(x, b1);
    gemm2_mma_kernel<<<dim3(FF / 256, BT / 128), 512, G2_TOTAL>>>(x, b2, out);
    ln_kernel<<<BT, 128>>>(out, gamma, beta);
}

// round 5
// speedup vs baseline: 2.8835x; 1.1548x over previous
#include <cuda_runtime.h>
#include <cuda_bf16.h>
#include <cstdint>

// Problem dims
#define BT 16384   // B*T = 8*2048
#define TSEQ 2048
#define DD 512
#define HH 128
#define NK 7
#define FF 512
#define KF 3584    // NK*FF
#define KDIM2 896  // NK*HH

// Scratch (allocation-free rule: __device__ globals)
__device__ float g_rs[BT];
__device__ __nv_bfloat16 g_hhi[BT * HH];      // pre-split h (written by gemm1)
__device__ __nv_bfloat16 g_hlo[BT * HH];
__device__ __nv_bfloat16 g_Bhi[NK * FF * HH]; // W2T hi, [k][f][h]
__device__ __nv_bfloat16 g_Blo[NK * FF * HH];
__device__ __nv_bfloat16 g_W1hi[HH * DD];     // W1T hi  [h][d]
__device__ __nv_bfloat16 g_W1lo[HH * DD];

// ---------------------------------------------------------------------------
// Helpers (base sm_103-safe: ldmatrix / mma.sync / cp.async only)
// ---------------------------------------------------------------------------
__device__ __forceinline__ uint32_t smem_u32(const void* p) {
    uint32_t a;
    asm("{ .reg .u64 t; cvta.to.shared.u64 t, %1; cvt.u32.u64 %0, t; }" : "=r"(a) : "l"(p));
    return a;
}
__device__ __forceinline__ void ldsm_x4(uint32_t a, uint32_t* r) {
    asm volatile("ldmatrix.sync.aligned.m8n8.x4.shared.b16 {%0,%1,%2,%3}, [%4];"
                 : "=r"(r[0]), "=r"(r[1]), "=r"(r[2]), "=r"(r[3]) : "r"(a));
}
__device__ __forceinline__ void mma16816(float* c, const uint32_t* a,
                                         uint32_t b0, uint32_t b1) {
    asm volatile("mma.sync.aligned.m16n8k16.row.col.f32.bf16.bf16.f32 "
                 "{%0,%1,%2,%3}, {%4,%5,%6,%7}, {%8,%9}, {%0,%1,%2,%3};"
                 : "+f"(c[0]), "+f"(c[1]), "+f"(c[2]), "+f"(c[3])
                 : "r"(a[0]), "r"(a[1]), "r"(a[2]), "r"(a[3]), "r"(b0), "r"(b1));
}
#define CP_ASYNC16(dst, src) \
    asm volatile("cp.async.cg.shared.global [%0], [%1], 16;" :: "r"(dst), "l"(src))
#define CP_COMMIT() asm volatile("cp.async.commit_group;" ::: "memory")
#define CP_WAIT(n)  asm volatile("cp.async.wait_group %0;" :: "n"(n) : "memory")
#define SWZ(o) ((o) ^ (((o) >> 3) & 0x70))

// fast truncation split: a = hi(bf16, truncated) + lo(bf16, RN of exact rem)
__device__ __forceinline__ void split4f(float a0, float a1, float a2, float a3,
                                        uint2& wh, uint2& wl) {
    uint32_t u0 = __float_as_uint(a0) & 0xFFFF0000u;
    uint32_t u1 = __float_as_uint(a1) & 0xFFFF0000u;
    uint32_t u2 = __float_as_uint(a2) & 0xFFFF0000u;
    uint32_t u3 = __float_as_uint(a3) & 0xFFFF0000u;
    wh.x = __byte_perm(u0, u1, 0x7632);
    wh.y = __byte_perm(u2, u3, 0x7632);
    float l0 = a0 - __uint_as_float(u0), l1 = a1 - __uint_as_float(u1);
    float l2 = a2 - __uint_as_float(u2), l3 = a3 - __uint_as_float(u3);
    asm("cvt.rn.bf16x2.f32 %0, %1, %2;" : "=r"(wl.x) : "f"(l1), "f"(l0));
    asm("cvt.rn.bf16x2.f32 %0, %1, %2;" : "=r"(wl.y) : "f"(l3), "f"(l2));
}
__device__ __forceinline__ void split2f(float a0, float a1, uint32_t& h, uint32_t& l) {
    uint32_t u0 = __float_as_uint(a0) & 0xFFFF0000u;
    uint32_t u1 = __float_as_uint(a1) & 0xFFFF0000u;
    h = __byte_perm(u0, u1, 0x7632);
    float l0 = a0 - __uint_as_float(u0), l1 = a1 - __uint_as_float(u1);
    asm("cvt.rn.bf16x2.f32 %0, %1, %2;" : "=r"(l) : "f"(l1), "f"(l0));
}

// ---------------------------------------------------------------------------
// Kernel 1: per-token channel rowsum
// ---------------------------------------------------------------------------
__global__ void rowsum_kernel(const float* __restrict__ x) {
    int row = blockIdx.x * 8 + threadIdx.y;
    int lane = threadIdx.x;
    const float4* xr = (const float4*)(x + (size_t)row * DD);
    float s = 0.f;
#pragma unroll
    for (int j = lane; j < DD / 4; j += 32) {
        float4 v = xr[j];
        s += (v.x + v.y) + (v.z + v.w);
    }
#pragma unroll
    for (int o = 16; o; o >>= 1) s += __shfl_xor_sync(0xffffffffu, s, o);
    if (lane == 0) g_rs[row] = s;
}

// ---------------------------------------------------------------------------
// Prep kernels: W1T split, W2T split re-laid out to [k][f][h]
// ---------------------------------------------------------------------------
__global__ __launch_bounds__(256) void prep_w1_kernel(const float* __restrict__ W1) {
    int idx = blockIdx.x * 256 + threadIdx.x;  // 65536, d fastest
    int h = idx >> 9, d = idx & 511;
    float v = W1[(size_t)d * HH + h];
    __nv_bfloat16 hi = __float2bfloat16(v);
    g_W1hi[idx] = hi;
    g_W1lo[idx] = __float2bfloat16(v - __bfloat162float(hi));
}
__global__ __launch_bounds__(256) void prep_w2_kernel(const float* __restrict__ W2) {
    int idx = blockIdx.x * 256 + threadIdx.x;  // NK*FF*HH = 458752, h fastest
    int h = idx & 127;
    int rest = idx >> 7;
    int f = rest & 511, k = rest >> 9;
    float v = W2[(size_t)h * KF + k * FF + f];
    __nv_bfloat16 hi = __float2bfloat16(v);
    g_Bhi[idx] = hi;
    g_Blo[idx] = __float2bfloat16(v - __bfloat162float(hi));
}

// ---------------------------------------------------------------------------
// GEMM1: h = relu(x @ W1 + b1), epilogue stores pre-split bf16 hi/lo
// CTA: 64 rows x 128 cols(H), 256 thr, warp tile 32x32, K=512 in 8 chunks
// ---------------------------------------------------------------------------
#define G1_STAGE 49152
#define G1_TOTAL 98304
__global__ __launch_bounds__(256, 2) void gemm1_mma_kernel(
    const float* __restrict__ x, const float* __restrict__ b1) {
    extern __shared__ char smem[];
    uint32_t sb = smem_u32(smem);
    int tid = threadIdx.x;
    int warp = tid >> 5, lane = tid & 31;
    int wm = warp & 1, wn = warp >> 1;
    int rowBase = blockIdx.x * 64;

    float acc[2][4][4];
#pragma unroll
    for (int a = 0; a < 2; a++)
#pragma unroll
        for (int b = 0; b < 4; b++)
#pragma unroll
            for (int cc = 0; cc < 4; cc++) acc[a][b][cc] = 0.f;

    auto build = [&](int c, int s) {
        char* ah = smem + s * G1_STAGE;           // 64x64 bf16 = 8KB
        char* al = ah + 8192;
        int p0 = c * 64;
#pragma unroll
        for (int i = 0; i < 4; i++) {
            int lin = i * 256 + tid;
            int row = lin >> 4, c4 = lin & 15;
            float4 v = *(const float4*)(x + (size_t)(rowBase + row) * DD + p0 + c4 * 4);
            uint2 wh, wl;
            split4f(v.x, v.y, v.z, v.w, wh, wl);
            uint32_t sw = SWZ(row * 128 + c4 * 8);
            *(uint2*)(ah + sw) = wh;
            *(uint2*)(al + sw) = wl;
        }
        uint32_t bh_s = sb + s * G1_STAGE + 16384;
        uint32_t bl_s = bh_s + 16384;
#pragma unroll
        for (int i = 0; i < 4; i++) {
            int lin = i * 256 + tid;
            int row = lin >> 3, c16 = lin & 7;
            uint32_t sw = SWZ(row * 128 + c16 * 16);
            size_t src = (size_t)row * DD + p0 + c16 * 8;
            CP_ASYNC16(bh_s + sw, g_W1hi + src);
            CP_ASYNC16(bl_s + sw, g_W1lo + src);
        }
        CP_COMMIT();
    };

    build(0, 0);
    for (int c = 0; c < 8; c++) {
        int s = c & 1;
        CP_WAIT(0);
        __syncthreads();
        if (c < 7) build(c + 1, s ^ 1);
        uint32_t ah_s = sb + s * G1_STAGE;
        uint32_t al_s = ah_s + 8192;
        uint32_t bh_s = ah_s + 16384;
        uint32_t bl_s = ah_s + 32768;
        int r = lane & 15, half = lane >> 4;
#pragma unroll
        for (int k16 = 0; k16 < 4; k16++) {
            int kc = k16 * 32 + half * 16;
            uint32_t ah[2][4], al[2][4], bh[2][4], bl[2][4];
#pragma unroll
            for (int mt = 0; mt < 2; mt++) {
                uint32_t o = SWZ((wm * 32 + mt * 16 + r) * 128 + kc);
                ldsm_x4(ah_s + o, ah[mt]);
                ldsm_x4(al_s + o, al[mt]);
            }
#pragma unroll
            for (int g = 0; g < 2; g++) {
                uint32_t o = SWZ((wn * 32 + g * 16 + r) * 128 + kc);
                ldsm_x4(bh_s + o, bh[g]);
                ldsm_x4(bl_s + o, bl[g]);
            }
#pragma unroll
            for (int mt = 0; mt < 2; mt++)
#pragma unroll
                for (int nt = 0; nt < 4; nt++) {
                    int g = nt >> 1, i2 = nt & 1;
                    mma16816(acc[mt][nt], ah[mt], bh[g][i2], bh[g][i2 + 2]);
                    mma16816(acc[mt][nt], ah[mt], bl[g][i2], bl[g][i2 + 2]);
                    mma16816(acc[mt][nt], al[mt], bh[g][i2], bh[g][i2 + 2]);
                }
        }
    }

    // epilogue: relu(acc + b1), split to bf16 hi/lo -> g_hhi/g_hlo
    int r = lane >> 2, cp2 = (lane & 3) * 2;
#pragma unroll
    for (int mt = 0; mt < 2; mt++) {
        int row0 = wm * 32 + mt * 16 + r;
        size_t off0 = (size_t)(rowBase + row0) * HH;
        size_t off1 = off0 + 8 * HH;
#pragma unroll
        for (int nt = 0; nt < 4; nt++) {
            int col = wn * 32 + nt * 8 + cp2;
            float2 bb = *(const float2*)(b1 + col);
            float v00 = fmaxf(acc[mt][nt][0] + bb.x, 0.f);
            float v01 = fmaxf(acc[mt][nt][1] + bb.y, 0.f);
            float v10 = fmaxf(acc[mt][nt][2] + bb.x, 0.f);
            float v11 = fmaxf(acc[mt][nt][3] + bb.y, 0.f);
            uint32_t h0, l0, h1, l1;
            split2f(v00, v01, h0, l0);
            split2f(v10, v11, h1, l1);
            *(uint32_t*)(g_hhi + off0 + col) = h0;
            *(uint32_t*)(g_hlo + off0 + col) = l0;
            *(uint32_t*)(g_hhi + off1 + col) = h1;
            *(uint32_t*)(g_hlo + off1 + col) = l1;
        }
    }
}

// ---------------------------------------------------------------------------
// GEMM2: out = x + sum_k diag(rs_k) * (h @ W2_k) + rs-window bias
// CTA: 128 rows x 128 f, 512 thr, 16 warps (4Mx4N), warp tile 32x32
// A (h hi/lo, K=128) loaded ONCE via cp.async; B per-tap double-buffered.
// Per tap: fresh acc over K=128, then acc2 += rs[row+tap]*acc (fp32).
// ---------------------------------------------------------------------------
#define G2_SMRS 0
#define G2_SMB2 1024        // 7*128 floats
#define G2_SMA  8192        // Ahi 32KB @ +0, Alo 32KB @ +32768
#define G2_SMB  73728       // stage s: Bhi 32KB, Blo 32KB; 2 stages
#define G2_TOTAL 204800
__global__ __launch_bounds__(512, 1) void gemm2_mma_kernel(
    const float* __restrict__ x, const float* __restrict__ b2,
    float* __restrict__ out) {
    extern __shared__ char smem[];
    uint32_t sb = smem_u32(smem);
    int tid = threadIdx.x;
    int warp = tid >> 5, lane = tid & 31;
    int wm = warp & 3, wn = warp >> 2;
    int rowBase = blockIdx.y * 128;
    int fBase = blockIdx.x * 128;

    float* rs_s = (float*)(smem + G2_SMRS);
    float* b2_s = (float*)(smem + G2_SMB2);
    int bstart = (rowBase / TSEQ) * TSEQ;
    if (tid < 136) {
        int gi = rowBase + tid - 3;
        float v = 0.f;
        if (tid < 134 && gi >= bstart && gi < bstart + TSEQ) v = g_rs[gi];
        rs_s[tid] = v;
    }
    for (int i = tid; i < NK * 128; i += 512)
        b2_s[i] = b2[(i >> 7) * FF + fBase + (i & 127)];

    // A tile: 128x128 bf16 hi/lo via cp.async (two 64-col sub-tiles each)
    {
        uint32_t ahi = sb + G2_SMA, alo = ahi + 32768;
#pragma unroll
        for (int i = 0; i < 4; i++) {
            int lin = i * 512 + tid;
            int row = lin >> 4, c16 = lin & 15;
            uint32_t dsw = (c16 >> 3) * 16384 + SWZ(row * 128 + (c16 & 7) * 16);
            size_t src = (size_t)(rowBase + row) * HH + c16 * 8;
            CP_ASYNC16(ahi + dsw, g_hhi + src);
            CP_ASYNC16(alo + dsw, g_hlo + src);
        }
    }
    // B tap 0 into stage 0 (same commit group as A)
    auto issueB = [&](int tap, int s) {
        uint32_t bhi = sb + G2_SMB + s * 65536, blo = bhi + 32768;
#pragma unroll
        for (int i = 0; i < 4; i++) {
            int lin = i * 512 + tid;
            int row = lin >> 4, c16 = lin & 15;
            uint32_t dsw = (c16 >> 3) * 16384 + SWZ(row * 128 + (c16 & 7) * 16);
            size_t src = ((size_t)tap * FF + fBase + row) * HH + c16 * 8;
            CP_ASYNC16(bhi + dsw, g_Bhi + src);
            CP_ASYNC16(blo + dsw, g_Blo + src);
        }
    };
    issueB(0, 0);
    CP_COMMIT();

    float acc2[2][4][4];
#pragma unroll
    for (int a = 0; a < 2; a++)
#pragma unroll
        for (int b = 0; b < 4; b++)
#pragma unroll
            for (int cc = 0; cc < 4; cc++) acc2[a][b][cc] = 0.f;

    int r = lane & 15, half = lane >> 4;
    int rr = lane >> 2;

    for (int tap = 0; tap < NK; tap++) {
        int s = tap & 1;
        __syncthreads();                 // stage s^1 free (prev MMA reads done)
        if (tap < 6) { issueB(tap + 1, s ^ 1); CP_COMMIT(); }
        if (tap < 6) { CP_WAIT(1); } else { CP_WAIT(0); }
        __syncthreads();                 // B(tap) (+A at tap0) visible to all

        float acc[2][4][4];
#pragma unroll
        for (int a = 0; a < 2; a++)
#pragma unroll
            for (int b = 0; b < 4; b++)
#pragma unroll
                for (int cc = 0; cc < 4; cc++) acc[a][b][cc] = 0.f;

        uint32_t ahi_s = sb + G2_SMA, alo_s = ahi_s + 32768;
        uint32_t bhi_s = sb + G2_SMB + s * 65536, blo_s = bhi_s + 32768;
#pragma unroll
        for (int k16 = 0; k16 < 8; k16++) {
            int kcb = k16 * 32 + half * 16;       // byte col 0..255
            uint32_t sub = (kcb >> 7) * 16384;
            int within = kcb & 127;
            uint32_t ah[2][4], al[2][4], bh[2][4], bl[2][4];
#pragma unroll
            for (int mt = 0; mt < 2; mt++) {
                uint32_t o = sub + SWZ((wm * 32 + mt * 16 + r) * 128 + within);
                ldsm_x4(ahi_s + o, ah[mt]);
                ldsm_x4(alo_s + o, al[mt]);
            }
#pragma unroll
            for (int g = 0; g < 2; g++) {
                uint32_t o = sub + SWZ((wn * 32 + g * 16 + r) * 128 + within);
                ldsm_x4(bhi_s + o, bh[g]);
                ldsm_x4(blo_s + o, bl[g]);
            }
#pragma unroll
            for (int mt = 0; mt < 2; mt++)
#pragma unroll
                for (int nt = 0; nt < 4; nt++) {
                    int g = nt >> 1, i2 = nt & 1;
                    mma16816(acc[mt][nt], ah[mt], bh[g][i2], bh[g][i2 + 2]);
                    mma16816(acc[mt][nt], ah[mt], bl[g][i2], bl[g][i2 + 2]);
                    mma16816(acc[mt][nt], al[mt], bh[g][i2], bh[g][i2 + 2]);
                }
        }
        // fold tap: acc2 += rs[row+tap] * acc
#pragma unroll
        for (int mt = 0; mt < 2; mt++) {
            int rloc = wm * 32 + mt * 16 + rr;
            float rv0 = rs_s[rloc + tap];
            float rv1 = rs_s[rloc + 8 + tap];
#pragma unroll
            for (int nt = 0; nt < 4; nt++) {
                acc2[mt][nt][0] = fmaf(rv0, acc[mt][nt][0], acc2[mt][nt][0]);
                acc2[mt][nt][1] = fmaf(rv0, acc[mt][nt][1], acc2[mt][nt][1]);
                acc2[mt][nt][2] = fmaf(rv1, acc[mt][nt][2], acc2[mt][nt][2]);
                acc2[mt][nt][3] = fmaf(rv1, acc[mt][nt][3], acc2[mt][nt][3]);
            }
        }
    }

    // epilogue: + rs-window bias + residual, write pre-LN y
    int cp2 = (lane & 3) * 2;
#pragma unroll
    for (int mt = 0; mt < 2; mt++) {
        int row0 = wm * 32 + mt * 16 + rr;
        int row1 = row0 + 8;
        float rv0[NK], rv1[NK];
#pragma unroll
        for (int k = 0; k < NK; k++) { rv0[k] = rs_s[row0 + k]; rv1[k] = rs_s[row1 + k]; }
        const float* x0 = x + (size_t)(rowBase + row0) * DD + fBase;
        const float* x1 = x0 + 8 * DD;
        float* o0 = out + (size_t)(rowBase + row0) * FF + fBase;
        float* o1 = o0 + 8 * FF;
#pragma unroll
        for (int nt = 0; nt < 4; nt++) {
            int col = wn * 32 + nt * 8 + cp2;
            float b00 = 0.f, b01 = 0.f, b10 = 0.f, b11 = 0.f;
#pragma unroll
            for (int k = 0; k < NK; k++) {
                float2 bb = *(const float2*)&b2_s[k * 128 + col];
                b00 = fmaf(rv0[k], bb.x, b00);
                b01 = fmaf(rv0[k], bb.y, b01);
                b10 = fmaf(rv1[k], bb.x, b10);
                b11 = fmaf(rv1[k], bb.y, b11);
            }
            float2 xv0 = *(const float2*)(x0 + col);
            float2 xv1 = *(const float2*)(x1 + col);
            float2 v0, v1;
            v0.x = acc2[mt][nt][0] + xv0.x + b00;
            v0.y = acc2[mt][nt][1] + xv0.y + b01;
            v1.x = acc2[mt][nt][2] + xv1.x + b10;
            v1.y = acc2[mt][nt][3] + xv1.y + b11;
            *(float2*)(o0 + col) = v0;
            *(float2*)(o1 + col) = v1;
        }
    }
}

// ---------------------------------------------------------------------------
// Kernel 4: in-place LayerNorm(eps=1e-3) + relu
// ---------------------------------------------------------------------------
__global__ __launch_bounds__(128) void ln_kernel(
    float* __restrict__ out, const float* __restrict__ gamma,
    const float* __restrict__ beta) {
    int row = blockIdx.x;
    int tid = threadIdx.x;
    float4 v = *(const float4*)(out + (size_t)row * FF + tid * 4);
    float s = (v.x + v.y) + (v.z + v.w);
    float s2 = (v.x * v.x + v.y * v.y) + (v.z * v.z + v.w * v.w);
#pragma unroll
    for (int o = 16; o; o >>= 1) {
        s += __shfl_xor_sync(0xffffffffu, s, o);
        s2 += __shfl_xor_sync(0xffffffffu, s2, o);
    }
    __shared__ float sred[8];
    int w = tid >> 5;
    if ((tid & 31) == 0) { sred[w] = s; sred[4 + w] = s2; }
    __syncthreads();
    s = (sred[0] + sred[1]) + (sred[2] + sred[3]);
    s2 = (sred[4] + sred[5]) + (sred[6] + sred[7]);
    float mean = s * (1.f / FF);
    float var = s2 * (1.f / FF) - mean * mean;
    float inv = rsqrtf(var + 1e-3f);
    float4 g = *(const float4*)(gamma + tid * 4);
    float4 b = *(const float4*)(beta + tid * 4);
    float4 o;
    o.x = fmaxf((v.x - mean) * inv * g.x + b.x, 0.f);
    o.y = fmaxf((v.y - mean) * inv * g.y + b.y, 0.f);
    o.z = fmaxf((v.z - mean) * inv * g.z + b.z, 0.f);
    o.w = fmaxf((v.w - mean) * inv * g.w + b.w, 0.f);
    *(float4*)(out + (size_t)row * FF + tid * 4) = o;
}

// ---------------------------------------------------------------------------
extern "C" void kernel_launch(void* const* d_in, const int* in_sizes, int n_in,
                              void* d_out, int out_size) {
    const float* x     = (const float*)d_in[0];
    const float* W1    = (const float*)d_in[1];
    const float* b1    = (const float*)d_in[2];
    const float* W2    = (const float*)d_in[3];
    const float* b2    = (const float*)d_in[4];
    const float* gamma = (const float*)d_in[5];
    const float* beta  = (const float*)d_in[6];
    float* out = (float*)d_out;

    cudaFuncSetAttribute(gemm1_mma_kernel,
                         cudaFuncAttributeMaxDynamicSharedMemorySize, G1_TOTAL);
    cudaFuncSetAttribute(gemm2_mma_kernel,
                         cudaFuncAttributeMaxDynamicSharedMemorySize, G2_TOTAL);

    rowsum_kernel<<<BT / 8, dim3(32, 8)>>>(x);
    prep_w1_kernel<<<(HH * DD) / 256, 256>>>(W1);
    prep_w2_kernel<<<(NK * FF * HH) / 256, 256>>>(W2);
    gemm1_mma_kernel<<<BT / 64, 256, G1_TOTAL>>>(x, b1);
    gemm2_mma_kernel<<<dim3(FF / 128, BT / 128), 512, G2_TOTAL>>>(x, b2, out);
    ln_kernel<<<BT, 128>>>(out, gamma, beta);
}

// round 6
// speedup vs baseline: 3.7566x; 1.3028x over previous
#include <cuda_runtime.h>
#include <cuda_fp16.h>
#include <cstdint>

// Problem dims
#define BT 16384   // B*T = 8*2048
#define TSEQ 2048
#define DD 512
#define HH 128
#define NK 7
#define FF 512
#define KF 3584    // NK*FF

// Scratch (allocation-free rule: __device__ globals)
__device__ float g_rs[BT];
__device__ __half g_x16[BT * DD];            // fp16 copy of x
__device__ __half g_h16[BT * HH];            // fp16 h (written by gemm1)
__device__ __half g_W1hi[HH * DD];           // W1T hi  [h][d]
__device__ __half g_W1lo[HH * DD];
__device__ __half g_Bhi[NK * FF * HH];       // W2T hi, [k][f][h]
__device__ __half g_Blo[NK * FF * HH];

// ---------------------------------------------------------------------------
// Helpers (base sm_103-safe: ldmatrix / mma.sync / cp.async only)
// ---------------------------------------------------------------------------
__device__ __forceinline__ uint32_t smem_u32(const void* p) {
    uint32_t a;
    asm("{ .reg .u64 t; cvta.to.shared.u64 t, %1; cvt.u32.u64 %0, t; }" : "=r"(a) : "l"(p));
    return a;
}
__device__ __forceinline__ void ldsm_x4(uint32_t a, uint32_t* r) {
    asm volatile("ldmatrix.sync.aligned.m8n8.x4.shared.b16 {%0,%1,%2,%3}, [%4];"
                 : "=r"(r[0]), "=r"(r[1]), "=r"(r[2]), "=r"(r[3]) : "r"(a));
}
__device__ __forceinline__ void mma16816(float* c, const uint32_t* a,
                                         uint32_t b0, uint32_t b1) {
    asm volatile("mma.sync.aligned.m16n8k16.row.col.f32.f16.f16.f32 "
                 "{%0,%1,%2,%3}, {%4,%5,%6,%7}, {%8,%9}, {%0,%1,%2,%3};"
                 : "+f"(c[0]), "+f"(c[1]), "+f"(c[2]), "+f"(c[3])
                 : "r"(a[0]), "r"(a[1]), "r"(a[2]), "r"(a[3]), "r"(b0), "r"(b1));
}
#define CP_ASYNC16(dst, src) \
    asm volatile("cp.async.cg.shared.global [%0], [%1], 16;" :: "r"(dst), "l"(src))
#define CP_COMMIT() asm volatile("cp.async.commit_group;" ::: "memory")
#define CP_WAIT(n)  asm volatile("cp.async.wait_group %0;" :: "n"(n) : "memory")
#define SWZ(o) ((o) ^ (((o) >> 3) & 0x70))

// ---------------------------------------------------------------------------
// prep_x: x -> fp16 copy + per-token rowsum (fused)
// ---------------------------------------------------------------------------
__global__ void prep_x_kernel(const float* __restrict__ x) {
    int row = blockIdx.x * 8 + threadIdx.y;
    int lane = threadIdx.x;
    const float4* xr = (const float4*)(x + (size_t)row * DD);
    __half* dst = g_x16 + (size_t)row * DD;
    float s = 0.f;
#pragma unroll
    for (int j = lane; j < DD / 4; j += 32) {
        float4 v = xr[j];
        s += (v.x + v.y) + (v.z + v.w);
        __half2 p0 = __floats2half2_rn(v.x, v.y);
        __half2 p1 = __floats2half2_rn(v.z, v.w);
        uint2 w;
        w.x = *(uint32_t*)&p0; w.y = *(uint32_t*)&p1;
        *(uint2*)(dst + j * 4) = w;
    }
#pragma unroll
    for (int o = 16; o; o >>= 1) s += __shfl_xor_sync(0xffffffffu, s, o);
    if (lane == 0) g_rs[row] = s;
}

// ---------------------------------------------------------------------------
// prep weights: transpose + fp16 hi/lo split
// ---------------------------------------------------------------------------
__global__ __launch_bounds__(256) void prep_w1_kernel(const float* __restrict__ W1) {
    int idx = blockIdx.x * 256 + threadIdx.x;  // 65536, d fastest
    int h = idx >> 9, d = idx & 511;
    float v = W1[(size_t)d * HH + h];
    __half hi = __float2half_rn(v);
    g_W1hi[idx] = hi;
    g_W1lo[idx] = __float2half_rn(v - __half2float(hi));
}
__global__ __launch_bounds__(256) void prep_w2_kernel(const float* __restrict__ W2) {
    int idx = blockIdx.x * 256 + threadIdx.x;  // NK*FF*HH = 458752, h fastest
    int h = idx & 127;
    int rest = idx >> 7;
    int f = rest & 511, k = rest >> 9;
    float v = W2[(size_t)h * KF + k * FF + f];
    __half hi = __float2half_rn(v);
    g_Bhi[idx] = hi;
    g_Blo[idx] = __float2half_rn(v - __half2float(hi));
}

// ---------------------------------------------------------------------------
// GEMM1: h = relu(x @ W1 + b1), fp16 2-chain (A single, B hi/lo)
// CTA: 64 rows x 128 cols(H), 256 thr, warp 32x32, K=512 in 8 chunks of 64
// stage: A 8KB + Bhi 16KB + Blo 16KB = 40KB; double-buffered, all cp.async
// ---------------------------------------------------------------------------
#define G1_STAGE 40960
#define G1_TOTAL 81920
__global__ __launch_bounds__(256, 2) void gemm1_mma_kernel(
    const float* __restrict__ b1) {
    extern __shared__ char smem[];
    uint32_t sb = smem_u32(smem);
    int tid = threadIdx.x;
    int warp = tid >> 5, lane = tid & 31;
    int wm = warp & 1, wn = warp >> 1;
    int rowBase = blockIdx.x * 64;

    float acc[2][4][4];
#pragma unroll
    for (int a = 0; a < 2; a++)
#pragma unroll
        for (int b = 0; b < 4; b++)
#pragma unroll
            for (int cc = 0; cc < 4; cc++) acc[a][b][cc] = 0.f;

    auto build = [&](int c, int s) {
        uint32_t a_s = sb + s * G1_STAGE;
        int p0 = c * 64;
        // A: 64x64 fp16, 512 chunks / 256 thr = 2 iters
#pragma unroll
        for (int i = 0; i < 2; i++) {
            int lin = i * 256 + tid;
            int row = lin >> 3, c16 = lin & 7;
            CP_ASYNC16(a_s + SWZ(row * 128 + c16 * 16),
                       g_x16 + (size_t)(rowBase + row) * DD + p0 + c16 * 8);
        }
        // B: W1T 128x64 hi/lo
        uint32_t bh_s = a_s + 8192, bl_s = a_s + 24576;
#pragma unroll
        for (int i = 0; i < 4; i++) {
            int lin = i * 256 + tid;
            int row = lin >> 3, c16 = lin & 7;
            uint32_t sw = SWZ(row * 128 + c16 * 16);
            size_t src = (size_t)row * DD + p0 + c16 * 8;
            CP_ASYNC16(bh_s + sw, g_W1hi + src);
            CP_ASYNC16(bl_s + sw, g_W1lo + src);
        }
        CP_COMMIT();
    };

    build(0, 0);
    for (int c = 0; c < 8; c++) {
        int s = c & 1;
        CP_WAIT(0);
        __syncthreads();
        if (c < 7) build(c + 1, s ^ 1);
        uint32_t a_s = sb + s * G1_STAGE;
        uint32_t bh_s = a_s + 8192;
        uint32_t bl_s = a_s + 24576;
        int r = lane & 15, half = lane >> 4;
#pragma unroll
        for (int k16 = 0; k16 < 4; k16++) {
            int kc = k16 * 32 + half * 16;
            uint32_t ah[2][4], bh[2][4], bl[2][4];
#pragma unroll
            for (int mt = 0; mt < 2; mt++)
                ldsm_x4(a_s + SWZ((wm * 32 + mt * 16 + r) * 128 + kc), ah[mt]);
#pragma unroll
            for (int g = 0; g < 2; g++) {
                uint32_t o = SWZ((wn * 32 + g * 16 + r) * 128 + kc);
                ldsm_x4(bh_s + o, bh[g]);
                ldsm_x4(bl_s + o, bl[g]);
            }
#pragma unroll
            for (int mt = 0; mt < 2; mt++)
#pragma unroll
                for (int nt = 0; nt < 4; nt++) {
                    int g = nt >> 1, i2 = nt & 1;
                    mma16816(acc[mt][nt], ah[mt], bh[g][i2], bh[g][i2 + 2]);
                    mma16816(acc[mt][nt], ah[mt], bl[g][i2], bl[g][i2 + 2]);
                }
        }
    }

    // epilogue: relu(acc + b1) -> fp16 g_h16
    int r = lane >> 2, cp2 = (lane & 3) * 2;
#pragma unroll
    for (int mt = 0; mt < 2; mt++) {
        int row0 = wm * 32 + mt * 16 + r;
        size_t off0 = (size_t)(rowBase + row0) * HH;
        size_t off1 = off0 + 8 * HH;
#pragma unroll
        for (int nt = 0; nt < 4; nt++) {
            int col = wn * 32 + nt * 8 + cp2;
            float2 bb = *(const float2*)(b1 + col);
            __half2 h0 = __floats2half2_rn(fmaxf(acc[mt][nt][0] + bb.x, 0.f),
                                           fmaxf(acc[mt][nt][1] + bb.y, 0.f));
            __half2 h1 = __floats2half2_rn(fmaxf(acc[mt][nt][2] + bb.x, 0.f),
                                           fmaxf(acc[mt][nt][3] + bb.y, 0.f));
            *(uint32_t*)(g_h16 + off0 + col) = *(uint32_t*)&h0;
            *(uint32_t*)(g_h16 + off1 + col) = *(uint32_t*)&h1;
        }
    }
}

// ---------------------------------------------------------------------------
// GEMM2: out = x + sum_k diag(rs_k) * (h @ W2_k) + rs-window bias
// CTA: 128 rows x 128 f, 512 thr, 16 warps (4Mx4N), warp tile 32x32
// A (h fp16, K=128) loaded ONCE; B (hi/lo) per-tap double-buffered.
// Per tap: fresh fp32 acc over K=128, then acc2 += rs[row+tap]*acc.
// ---------------------------------------------------------------------------
#define G2_SMRS 0
#define G2_SMB2 1024        // 7*128 floats
#define G2_SMA  8192        // A 32KB (two 64-col subtiles)
#define G2_SMB  40960       // stage s: Bhi 32KB, Blo 32KB; 2 stages
#define G2_TOTAL 172032
__global__ __launch_bounds__(512, 1) void gemm2_mma_kernel(
    const float* __restrict__ x, const float* __restrict__ b2,
    float* __restrict__ out) {
    extern __shared__ char smem[];
    uint32_t sb = smem_u32(smem);
    int tid = threadIdx.x;
    int warp = tid >> 5, lane = tid & 31;
    int wm = warp & 3, wn = warp >> 2;
    int rowBase = blockIdx.y * 128;
    int fBase = blockIdx.x * 128;

    float* rs_s = (float*)(smem + G2_SMRS);
    float* b2_s = (float*)(smem + G2_SMB2);
    int bstart = (rowBase / TSEQ) * TSEQ;
    if (tid < 136) {
        int gi = rowBase + tid - 3;
        float v = 0.f;
        if (tid < 134 && gi >= bstart && gi < bstart + TSEQ) v = g_rs[gi];
        rs_s[tid] = v;
    }
    for (int i = tid; i < NK * 128; i += 512)
        b2_s[i] = b2[(i >> 7) * FF + fBase + (i & 127)];

    // A: 128x128 fp16 via cp.async, two 64-col subtiles
    {
        uint32_t a_s = sb + G2_SMA;
#pragma unroll
        for (int i = 0; i < 4; i++) {
            int lin = i * 512 + tid;
            int row = lin >> 4, c16 = lin & 15;
            uint32_t dsw = (c16 >> 3) * 16384 + SWZ(row * 128 + (c16 & 7) * 16);
            CP_ASYNC16(a_s + dsw, g_h16 + (size_t)(rowBase + row) * HH + c16 * 8);
        }
    }
    auto issueB = [&](int tap, int s) {
        uint32_t bhi = sb + G2_SMB + s * 65536, blo = bhi + 32768;
#pragma unroll
        for (int i = 0; i < 4; i++) {
            int lin = i * 512 + tid;
            int row = lin >> 4, c16 = lin & 15;
            uint32_t dsw = (c16 >> 3) * 16384 + SWZ(row * 128 + (c16 & 7) * 16);
            size_t src = ((size_t)tap * FF + fBase + row) * HH + c16 * 8;
            CP_ASYNC16(bhi + dsw, g_Bhi + src);
            CP_ASYNC16(blo + dsw, g_Blo + src);
        }
    };
    issueB(0, 0);
    CP_COMMIT();

    float acc2[2][4][4];
#pragma unroll
    for (int a = 0; a < 2; a++)
#pragma unroll
        for (int b = 0; b < 4; b++)
#pragma unroll
            for (int cc = 0; cc < 4; cc++) acc2[a][b][cc] = 0.f;

    int r = lane & 15, half = lane >> 4;
    int rr = lane >> 2;

    for (int tap = 0; tap < NK; tap++) {
        int s = tap & 1;
        __syncthreads();                 // stage s^1 free (prev MMA reads done)
        if (tap < 6) { issueB(tap + 1, s ^ 1); CP_COMMIT(); }
        if (tap < 6) { CP_WAIT(1); } else { CP_WAIT(0); }
        __syncthreads();                 // B(tap) (+A at tap0) visible

        float acc[2][4][4];
#pragma unroll
        for (int a = 0; a < 2; a++)
#pragma unroll
            for (int b = 0; b < 4; b++)
#pragma unroll
                for (int cc = 0; cc < 4; cc++) acc[a][b][cc] = 0.f;

        uint32_t a_s = sb + G2_SMA;
        uint32_t bhi_s = sb + G2_SMB + s * 65536, blo_s = bhi_s + 32768;
#pragma unroll
        for (int k16 = 0; k16 < 8; k16++) {
            int kcb = k16 * 32 + half * 16;       // byte col 0..255
            uint32_t sub = (kcb >> 7) * 16384;
            int within = kcb & 127;
            uint32_t ah[2][4], bh[2][4], bl[2][4];
#pragma unroll
            for (int mt = 0; mt < 2; mt++)
                ldsm_x4(a_s + sub + SWZ((wm * 32 + mt * 16 + r) * 128 + within), ah[mt]);
#pragma unroll
            for (int g = 0; g < 2; g++) {
                uint32_t o = sub + SWZ((wn * 32 + g * 16 + r) * 128 + within);
                ldsm_x4(bhi_s + o, bh[g]);
                ldsm_x4(blo_s + o, bl[g]);
            }
#pragma unroll
            for (int mt = 0; mt < 2; mt++)
#pragma unroll
                for (int nt = 0; nt < 4; nt++) {
                    int g = nt >> 1, i2 = nt & 1;
                    mma16816(acc[mt][nt], ah[mt], bh[g][i2], bh[g][i2 + 2]);
                    mma16816(acc[mt][nt], ah[mt], bl[g][i2], bl[g][i2 + 2]);
                }
        }
        // fold tap: acc2 += rs[row+tap] * acc
#pragma unroll
        for (int mt = 0; mt < 2; mt++) {
            int rloc = wm * 32 + mt * 16 + rr;
            float rv0 = rs_s[rloc + tap];
            float rv1 = rs_s[rloc + 8 + tap];
#pragma unroll
            for (int nt = 0; nt < 4; nt++) {
                acc2[mt][nt][0] = fmaf(rv0, acc[mt][nt][0], acc2[mt][nt][0]);
                acc2[mt][nt][1] = fmaf(rv0, acc[mt][nt][1], acc2[mt][nt][1]);
                acc2[mt][nt][2] = fmaf(rv1, acc[mt][nt][2], acc2[mt][nt][2]);
                acc2[mt][nt][3] = fmaf(rv1, acc[mt][nt][3], acc2[mt][nt][3]);
            }
        }
    }

    // epilogue: + rs-window bias + residual, write pre-LN y
    int cp2 = (lane & 3) * 2;
#pragma unroll
    for (int mt = 0; mt < 2; mt++) {
        int row0 = wm * 32 + mt * 16 + rr;
        int row1 = row0 + 8;
        float rv0[NK], rv1[NK];
#pragma unroll
        for (int k = 0; k < NK; k++) { rv0[k] = rs_s[row0 + k]; rv1[k] = rs_s[row1 + k]; }
        const float* x0 = x + (size_t)(rowBase + row0) * DD + fBase;
        const float* x1 = x0 + 8 * DD;
        float* o0 = out + (size_t)(rowBase + row0) * FF + fBase;
        float* o1 = o0 + 8 * FF;
#pragma unroll
        for (int nt = 0; nt < 4; nt++) {
            int col = wn * 32 + nt * 8 + cp2;
            float b00 = 0.f, b01 = 0.f, b10 = 0.f, b11 = 0.f;
#pragma unroll
            for (int k = 0; k < NK; k++) {
                float2 bb = *(const float2*)&b2_s[k * 128 + col];
                b00 = fmaf(rv0[k], bb.x, b00);
                b01 = fmaf(rv0[k], bb.y, b01);
                b10 = fmaf(rv1[k], bb.x, b10);
                b11 = fmaf(rv1[k], bb.y, b11);
            }
            float2 xv0 = *(const float2*)(x0 + col);
            float2 xv1 = *(const float2*)(x1 + col);
            float2 v0, v1;
            v0.x = acc2[mt][nt][0] + xv0.x + b00;
            v0.y = acc2[mt][nt][1] + xv0.y + b01;
            v1.x = acc2[mt][nt][2] + xv1.x + b10;
            v1.y = acc2[mt][nt][3] + xv1.y + b11;
            *(float2*)(o0 + col) = v0;
            *(float2*)(o1 + col) = v1;
        }
    }
}

// ---------------------------------------------------------------------------
// LayerNorm(eps=1e-3) + relu, in place
// ---------------------------------------------------------------------------
__global__ __launch_bounds__(128) void ln_kernel(
    float* __restrict__ out, const float* __restrict__ gamma,
    const float* __restrict__ beta) {
    int row = blockIdx.x;
    int tid = threadIdx.x;
    float4 v = *(const float4*)(out + (size_t)row * FF + tid * 4);
    float s = (v.x + v.y) + (v.z + v.w);
    float s2 = (v.x * v.x + v.y * v.y) + (v.z * v.z + v.w * v.w);
#pragma unroll
    for (int o = 16; o; o >>= 1) {
        s += __shfl_xor_sync(0xffffffffu, s, o);
        s2 += __shfl_xor_sync(0xffffffffu, s2, o);
    }
    __shared__ float sred[8];
    int w = tid >> 5;
    if ((tid & 31) == 0) { sred[w] = s; sred[4 + w] = s2; }
    __syncthreads();
    s = (sred[0] + sred[1]) + (sred[2] + sred[3]);
    s2 = (sred[4] + sred[5]) + (sred[6] + sred[7]);
    float mean = s * (1.f / FF);
    float var = s2 * (1.f / FF) - mean * mean;
    float inv = rsqrtf(var + 1e-3f);
    float4 g = *(const float4*)(gamma + tid * 4);
    float4 b = *(const float4*)(beta + tid * 4);
    float4 o;
    o.x = fmaxf((v.x - mean) * inv * g.x + b.x, 0.f);
    o.y = fmaxf((v.y - mean) * inv * g.y + b.y, 0.f);
    o.z = fmaxf((v.z - mean) * inv * g.z + b.z, 0.f);
    o.w = fmaxf((v.w - mean) * inv * g.w + b.w, 0.f);
    *(float4*)(out + (size_t)row * FF + tid * 4) = o;
}

// ---------------------------------------------------------------------------
extern "C" void kernel_launch(void* const* d_in, const int* in_sizes, int n_in,
                              void* d_out, int out_size) {
    const float* x     = (const float*)d_in[0];
    const float* W1    = (const float*)d_in[1];
    const float* b1    = (const float*)d_in[2];
    const float* W2    = (const float*)d_in[3];
    const float* b2    = (const float*)d_in[4];
    const float* gamma = (const float*)d_in[5];
    const float* beta  = (const float*)d_in[6];
    float* out = (float*)d_out;

    cudaFuncSetAttribute(gemm1_mma_kernel,
                         cudaFuncAttributeMaxDynamicSharedMemorySize, G1_TOTAL);
    cudaFuncSetAttribute(gemm2_mma_kernel,
                         cudaFuncAttributeMaxDynamicSharedMemorySize, G2_TOTAL);

    prep_x_kernel<<<BT / 8, dim3(32, 8)>>>(x);
    prep_w1_kernel<<<(HH * DD) / 256, 256>>>(W1);
    prep_w2_kernel<<<(NK * FF * HH) / 256, 256>>>(W2);
    gemm1_mma_kernel<<<BT / 64, 256, G1_TOTAL>>>(b1);
    gemm2_mma_kernel<<<dim3(FF / 128, BT / 128), 512, G2_TOTAL>>>(x, b2, out);
    ln_kernel<<<BT, 128>>>(out, gamma, beta);
}

// round 7
// speedup vs baseline: 5.3451x; 1.4229x over previous
#include <cuda_runtime.h>
#include <cuda_fp16.h>
#include <cstdint>

// Problem dims
#define BT 16384   // B*T = 8*2048
#define TSEQ 2048
#define DD 512
#define HH 128
#define NK 7
#define FF 512
#define KF 3584    // NK*FF

// Scratch (allocation-free rule: __device__ globals)
__device__ float g_rs[BT];
__device__ __half g_x16[BT * DD];            // fp16 copy of x
__device__ __half g_h16[BT * HH];            // fp16 h (written by gemm1)
__device__ __half g_W1h[HH * DD];            // W1T fp16  [h][d]
__device__ __half g_B16[NK * FF * HH];       // W2T fp16, [k][f][h]

// ---------------------------------------------------------------------------
// Helpers (base sm_103-safe: ldmatrix / mma.sync / cp.async only)
// ---------------------------------------------------------------------------
__device__ __forceinline__ uint32_t smem_u32(const void* p) {
    uint32_t a;
    asm("{ .reg .u64 t; cvta.to.shared.u64 t, %1; cvt.u32.u64 %0, t; }" : "=r"(a) : "l"(p));
    return a;
}
__device__ __forceinline__ void ldsm_x4(uint32_t a, uint32_t* r) {
    asm volatile("ldmatrix.sync.aligned.m8n8.x4.shared.b16 {%0,%1,%2,%3}, [%4];"
                 : "=r"(r[0]), "=r"(r[1]), "=r"(r[2]), "=r"(r[3]) : "r"(a));
}
__device__ __forceinline__ void mma16816(float* c, const uint32_t* a,
                                         uint32_t b0, uint32_t b1) {
    asm volatile("mma.sync.aligned.m16n8k16.row.col.f32.f16.f16.f32 "
                 "{%0,%1,%2,%3}, {%4,%5,%6,%7}, {%8,%9}, {%0,%1,%2,%3};"
                 : "+f"(c[0]), "+f"(c[1]), "+f"(c[2]), "+f"(c[3])
                 : "r"(a[0]), "r"(a[1]), "r"(a[2]), "r"(a[3]), "r"(b0), "r"(b1));
}
#define CP_ASYNC16(dst, src) \
    asm volatile("cp.async.cg.shared.global [%0], [%1], 16;" :: "r"(dst), "l"(src))
#define CP_COMMIT() asm volatile("cp.async.commit_group;" ::: "memory")
#define CP_WAIT(n)  asm volatile("cp.async.wait_group %0;" :: "n"(n) : "memory")
#define SWZ(o) ((o) ^ (((o) >> 3) & 0x70))

// ---------------------------------------------------------------------------
// prep_x: x -> fp16 copy + per-token rowsum (fused)
// ---------------------------------------------------------------------------
__global__ void prep_x_kernel(const float* __restrict__ x) {
    int row = blockIdx.x * 8 + threadIdx.y;
    int lane = threadIdx.x;
    const float4* xr = (const float4*)(x + (size_t)row * DD);
    __half* dst = g_x16 + (size_t)row * DD;
    float s = 0.f;
#pragma unroll
    for (int j = lane; j < DD / 4; j += 32) {
        float4 v = xr[j];
        s += (v.x + v.y) + (v.z + v.w);
        __half2 p0 = __floats2half2_rn(v.x, v.y);
        __half2 p1 = __floats2half2_rn(v.z, v.w);
        uint2 w;
        w.x = *(uint32_t*)&p0; w.y = *(uint32_t*)&p1;
        *(uint2*)(dst + j * 4) = w;
    }
#pragma unroll
    for (int o = 16; o; o >>= 1) s += __shfl_xor_sync(0xffffffffu, s, o);
    if (lane == 0) g_rs[row] = s;
}

// ---------------------------------------------------------------------------
// prep weights: transpose + fp16 RN
// ---------------------------------------------------------------------------
__global__ __launch_bounds__(256) void prep_w1_kernel(const float* __restrict__ W1) {
    int idx = blockIdx.x * 256 + threadIdx.x;  // 65536, d fastest
    int h = idx >> 9, d = idx & 511;
    g_W1h[idx] = __float2half_rn(W1[(size_t)d * HH + h]);
}
__global__ __launch_bounds__(256) void prep_w2_kernel(const float* __restrict__ W2) {
    int idx = blockIdx.x * 256 + threadIdx.x;  // NK*FF*HH = 458752, h fastest
    int h = idx & 127;
    int rest = idx >> 7;
    int f = rest & 511, k = rest >> 9;
    g_B16[idx] = __float2half_rn(W2[(size_t)h * KF + k * FF + f]);
}

// ---------------------------------------------------------------------------
// GEMM1: h = relu(x @ W1 + b1), single fp16 chain
// CTA: 64 rows x 128 cols(H), 256 thr, warp 32x32, K=512 in 8 chunks of 64
// stage: A 8KB + B 16KB = 24KB; double-buffered, all cp.async
// ---------------------------------------------------------------------------
#define G1_STAGE 24576
#define G1_TOTAL 49152
__global__ __launch_bounds__(256, 2) void gemm1_mma_kernel(
    const float* __restrict__ b1) {
    extern __shared__ char smem[];
    uint32_t sb = smem_u32(smem);
    int tid = threadIdx.x;
    int warp = tid >> 5, lane = tid & 31;
    int wm = warp & 1, wn = warp >> 1;
    int rowBase = blockIdx.x * 64;

    float acc[2][4][4];
#pragma unroll
    for (int a = 0; a < 2; a++)
#pragma unroll
        for (int b = 0; b < 4; b++)
#pragma unroll
            for (int cc = 0; cc < 4; cc++) acc[a][b][cc] = 0.f;

    auto build = [&](int c, int s) {
        uint32_t a_s = sb + s * G1_STAGE;
        int p0 = c * 64;
        // A: 64x64 fp16, 512 chunks / 256 thr = 2 iters
#pragma unroll
        for (int i = 0; i < 2; i++) {
            int lin = i * 256 + tid;
            int row = lin >> 3, c16 = lin & 7;
            CP_ASYNC16(a_s + SWZ(row * 128 + c16 * 16),
                       g_x16 + (size_t)(rowBase + row) * DD + p0 + c16 * 8);
        }
        // B: W1T 128x64 fp16
        uint32_t b_s = a_s + 8192;
#pragma unroll
        for (int i = 0; i < 4; i++) {
            int lin = i * 256 + tid;
            int row = lin >> 3, c16 = lin & 7;
            CP_ASYNC16(b_s + SWZ(row * 128 + c16 * 16),
                       g_W1h + (size_t)row * DD + p0 + c16 * 8);
        }
        CP_COMMIT();
    };

    build(0, 0);
    for (int c = 0; c < 8; c++) {
        int s = c & 1;
        CP_WAIT(0);
        __syncthreads();
        if (c < 7) build(c + 1, s ^ 1);
        uint32_t a_s = sb + s * G1_STAGE;
        uint32_t b_s = a_s + 8192;
        int r = lane & 15, half = lane >> 4;
#pragma unroll
        for (int k16 = 0; k16 < 4; k16++) {
            int kc = k16 * 32 + half * 16;
            uint32_t ah[2][4], bh[2][4];
#pragma unroll
            for (int mt = 0; mt < 2; mt++)
                ldsm_x4(a_s + SWZ((wm * 32 + mt * 16 + r) * 128 + kc), ah[mt]);
#pragma unroll
            for (int g = 0; g < 2; g++)
                ldsm_x4(b_s + SWZ((wn * 32 + g * 16 + r) * 128 + kc), bh[g]);
#pragma unroll
            for (int mt = 0; mt < 2; mt++)
#pragma unroll
                for (int nt = 0; nt < 4; nt++) {
                    int g = nt >> 1, i2 = nt & 1;
                    mma16816(acc[mt][nt], ah[mt], bh[g][i2], bh[g][i2 + 2]);
                }
        }
    }

    // epilogue: relu(acc + b1) -> fp16 g_h16
    int r = lane >> 2, cp2 = (lane & 3) * 2;
#pragma unroll
    for (int mt = 0; mt < 2; mt++) {
        int row0 = wm * 32 + mt * 16 + r;
        size_t off0 = (size_t)(rowBase + row0) * HH;
        size_t off1 = off0 + 8 * HH;
#pragma unroll
        for (int nt = 0; nt < 4; nt++) {
            int col = wn * 32 + nt * 8 + cp2;
            float2 bb = *(const float2*)(b1 + col);
            __half2 h0 = __floats2half2_rn(fmaxf(acc[mt][nt][0] + bb.x, 0.f),
                                           fmaxf(acc[mt][nt][1] + bb.y, 0.f));
            __half2 h1 = __floats2half2_rn(fmaxf(acc[mt][nt][2] + bb.x, 0.f),
                                           fmaxf(acc[mt][nt][3] + bb.y, 0.f));
            *(uint32_t*)(g_h16 + off0 + col) = *(uint32_t*)&h0;
            *(uint32_t*)(g_h16 + off1 + col) = *(uint32_t*)&h1;
        }
    }
}

// ---------------------------------------------------------------------------
// GEMM2: out = x + sum_k diag(rs_k) * (h @ W2_k) + rs-window bias
// CTA: 128 rows x 128 f, 512 thr, 16 warps (4Mx4N), warp tile 32x32
// A (h fp16, K=128) loaded ONCE; B per-tap TRIPLE-buffered (32KB/stage).
// Per tap: fresh fp32 acc over K=128, then acc2 += rs[row+tap]*acc.
// ---------------------------------------------------------------------------
#define G2_SMRS 0
#define G2_SMB2 1024        // 7*128 floats
#define G2_SMA  8192        // A 32KB (two 64-col subtiles)
#define G2_SMB  40960       // 3 stages x 32KB
#define G2_TOTAL 139264
__global__ __launch_bounds__(512, 1) void gemm2_mma_kernel(
    const float* __restrict__ x, const float* __restrict__ b2,
    float* __restrict__ out) {
    extern __shared__ char smem[];
    uint32_t sb = smem_u32(smem);
    int tid = threadIdx.x;
    int warp = tid >> 5, lane = tid & 31;
    int wm = warp & 3, wn = warp >> 2;
    int rowBase = blockIdx.y * 128;
    int fBase = blockIdx.x * 128;

    float* rs_s = (float*)(smem + G2_SMRS);
    float* b2_s = (float*)(smem + G2_SMB2);
    int bstart = (rowBase / TSEQ) * TSEQ;
    if (tid < 136) {
        int gi = rowBase + tid - 3;
        float v = 0.f;
        if (tid < 134 && gi >= bstart && gi < bstart + TSEQ) v = g_rs[gi];
        rs_s[tid] = v;
    }
    for (int i = tid; i < NK * 128; i += 512)
        b2_s[i] = b2[(i >> 7) * FF + fBase + (i & 127)];

    // A: 128x128 fp16 via cp.async, two 64-col subtiles
    {
        uint32_t a_s = sb + G2_SMA;
#pragma unroll
        for (int i = 0; i < 4; i++) {
            int lin = i * 512 + tid;
            int row = lin >> 4, c16 = lin & 15;
            uint32_t dsw = (c16 >> 3) * 16384 + SWZ(row * 128 + (c16 & 7) * 16);
            CP_ASYNC16(a_s + dsw, g_h16 + (size_t)(rowBase + row) * HH + c16 * 8);
        }
    }
    auto issueB = [&](int tap, int s) {
        uint32_t b_s = sb + G2_SMB + s * 32768;
#pragma unroll
        for (int i = 0; i < 2; i++) {
            int lin = i * 512 + tid;
            int row = lin >> 3, c16 = lin & 7;
            uint32_t dsw = SWZ(row * 128 + c16 * 16);
            // 128 rows x 128 cols fp16: two 64-col subtiles along K
            // lin covers rows 0..127 x c16 0..7 (first 64 cols)... need both
            CP_ASYNC16(b_s + (0) * 16384 + dsw,
                       g_B16 + ((size_t)tap * FF + fBase + row) * HH + c16 * 8);
            CP_ASYNC16(b_s + 1 * 16384 + dsw,
                       g_B16 + ((size_t)tap * FF + fBase + row) * HH + 64 + c16 * 8);
        }
        CP_COMMIT();
    };
    // prologue: A+B0 in group0, B1 in group1
    issueB(0, 0);
    issueB(1, 1);

    float acc2[2][4][4];
#pragma unroll
    for (int a = 0; a < 2; a++)
#pragma unroll
        for (int b = 0; b < 4; b++)
#pragma unroll
            for (int cc = 0; cc < 4; cc++) acc2[a][b][cc] = 0.f;

    int r = lane & 15, half = lane >> 4;
    int rr = lane >> 2;

    for (int tap = 0; tap < NK; tap++) {
        int s = tap - (tap / 3) * 3;     // tap % 3
        __syncthreads();                 // stage (tap+2)%3 reads (tap-1) done
        if (tap + 2 < NK) {
            int s2 = (tap + 2) - ((tap + 2) / 3) * 3;
            issueB(tap + 2, s2);
        }
        if (tap < 5) { CP_WAIT(2); } else if (tap == 5) { CP_WAIT(1); } else { CP_WAIT(0); }
        __syncthreads();                 // B(tap) (+A at tap0) visible

        float acc[2][4][4];
#pragma unroll
        for (int a = 0; a < 2; a++)
#pragma unroll
            for (int b = 0; b < 4; b++)
#pragma unroll
                for (int cc = 0; cc < 4; cc++) acc[a][b][cc] = 0.f;

        uint32_t a_s = sb + G2_SMA;
        uint32_t b_s = sb + G2_SMB + s * 32768;
#pragma unroll
        for (int k16 = 0; k16 < 8; k16++) {
            int kcb = k16 * 32 + half * 16;       // byte col 0..255
            uint32_t sub = (kcb >> 7) * 16384;
            int within = kcb & 127;
            uint32_t ah[2][4], bh[2][4];
#pragma unroll
            for (int mt = 0; mt < 2; mt++)
                ldsm_x4(a_s + sub + SWZ((wm * 32 + mt * 16 + r) * 128 + within), ah[mt]);
#pragma unroll
            for (int g = 0; g < 2; g++)
                ldsm_x4(b_s + sub + SWZ((wn * 32 + g * 16 + r) * 128 + within), bh[g]);
#pragma unroll
            for (int mt = 0; mt < 2; mt++)
#pragma unroll
                for (int nt = 0; nt < 4; nt++) {
                    int g = nt >> 1, i2 = nt & 1;
                    mma16816(acc[mt][nt], ah[mt], bh[g][i2], bh[g][i2 + 2]);
                }
        }
        // fold tap: acc2 += rs[row+tap] * acc
#pragma unroll
        for (int mt = 0; mt < 2; mt++) {
            int rloc = wm * 32 + mt * 16 + rr;
            float rv0 = rs_s[rloc + tap];
            float rv1 = rs_s[rloc + 8 + tap];
#pragma unroll
            for (int nt = 0; nt < 4; nt++) {
                acc2[mt][nt][0] = fmaf(rv0, acc[mt][nt][0], acc2[mt][nt][0]);
                acc2[mt][nt][1] = fmaf(rv0, acc[mt][nt][1], acc2[mt][nt][1]);
                acc2[mt][nt][2] = fmaf(rv1, acc[mt][nt][2], acc2[mt][nt][2]);
                acc2[mt][nt][3] = fmaf(rv1, acc[mt][nt][3], acc2[mt][nt][3]);
            }
        }
    }

    // epilogue: + rs-window bias + residual, write pre-LN y
    int cp2 = (lane & 3) * 2;
#pragma unroll
    for (int mt = 0; mt < 2; mt++) {
        int row0 = wm * 32 + mt * 16 + rr;
        int row1 = row0 + 8;
        float rv0[NK], rv1[NK];
#pragma unroll
        for (int k = 0; k < NK; k++) { rv0[k] = rs_s[row0 + k]; rv1[k] = rs_s[row1 + k]; }
        const float* x0 = x + (size_t)(rowBase + row0) * DD + fBase;
        const float* x1 = x0 + 8 * DD;
        float* o0 = out + (size_t)(rowBase + row0) * FF + fBase;
        float* o1 = o0 + 8 * FF;
#pragma unroll
        for (int nt = 0; nt < 4; nt++) {
            int col = wn * 32 + nt * 8 + cp2;
            float b00 = 0.f, b01 = 0.f, b10 = 0.f, b11 = 0.f;
#pragma unroll
            for (int k = 0; k < NK; k++) {
                float2 bb = *(const float2*)&b2_s[k * 128 + col];
                b00 = fmaf(rv0[k], bb.x, b00);
                b01 = fmaf(rv0[k], bb.y, b01);
                b10 = fmaf(rv1[k], bb.x, b10);
                b11 = fmaf(rv1[k], bb.y, b11);
            }
            float2 xv0 = *(const float2*)(x0 + col);
            float2 xv1 = *(const float2*)(x1 + col);
            float2 v0, v1;
            v0.x = acc2[mt][nt][0] + xv0.x + b00;
            v0.y = acc2[mt][nt][1] + xv0.y + b01;
            v1.x = acc2[mt][nt][2] + xv1.x + b10;
            v1.y = acc2[mt][nt][3] + xv1.y + b11;
            *(float2*)(o0 + col) = v0;
            *(float2*)(o1 + col) = v1;
        }
    }
}

// ---------------------------------------------------------------------------
// LayerNorm(eps=1e-3) + relu, in place
// ---------------------------------------------------------------------------
__global__ __launch_bounds__(128) void ln_kernel(
    float* __restrict__ out, const float* __restrict__ gamma,
    const float* __restrict__ beta) {
    int row = blockIdx.x;
    int tid = threadIdx.x;
    float4 v = *(const float4*)(out + (size_t)row * FF + tid * 4);
    float s = (v.x + v.y) + (v.z + v.w);
    float s2 = (v.x * v.x + v.y * v.y) + (v.z * v.z + v.w * v.w);
#pragma unroll
    for (int o = 16; o; o >>= 1) {
        s += __shfl_xor_sync(0xffffffffu, s, o);
        s2 += __shfl_xor_sync(0xffffffffu, s2, o);
    }
    __shared__ float sred[8];
    int w = tid >> 5;
    if ((tid & 31) == 0) { sred[w] = s; sred[4 + w] = s2; }
    __syncthreads();
    s = (sred[0] + sred[1]) + (sred[2] + sred[3]);
    s2 = (sred[4] + sred[5]) + (sred[6] + sred[7]);
    float mean = s * (1.f / FF);
    float var = s2 * (1.f / FF) - mean * mean;
    float inv = rsqrtf(var + 1e-3f);
    float4 g = *(const float4*)(gamma + tid * 4);
    float4 b = *(const float4*)(beta + tid * 4);
    float4 o;
    o.x = fmaxf((v.x - mean) * inv * g.x + b.x, 0.f);
    o.y = fmaxf((v.y - mean) * inv * g.y + b.y, 0.f);
    o.z = fmaxf((v.z - mean) * inv * g.z + b.z, 0.f);
    o.w = fmaxf((v.w - mean) * inv * g.w + b.w, 0.f);
    *(float4*)(out + (size_t)row * FF + tid * 4) = o;
}

// ---------------------------------------------------------------------------
extern "C" void kernel_launch(void* const* d_in, const int* in_sizes, int n_in,
                              void* d_out, int out_size) {
    const float* x     = (const float*)d_in[0];
    const float* W1    = (const float*)d_in[1];
    const float* b1    = (const float*)d_in[2];
    const float* W2    = (const float*)d_in[3];
    const float* b2    = (const float*)d_in[4];
    const float* gamma = (const float*)d_in[5];
    const float* beta  = (const float*)d_in[6];
    float* out = (float*)d_out;

    cudaFuncSetAttribute(gemm1_mma_kernel,
                         cudaFuncAttributeMaxDynamicSharedMemorySize, G1_TOTAL);
    cudaFuncSetAttribute(gemm2_mma_kernel,
                         cudaFuncAttributeMaxDynamicSharedMemorySize, G2_TOTAL);

    prep_x_kernel<<<BT / 8, dim3(32, 8)>>>(x);
    prep_w1_kernel<<<(HH * DD) / 256, 256>>>(W1);
    prep_w2_kernel<<<(NK * FF * HH) / 256, 256>>>(W2);
    gemm1_mma_kernel<<<BT / 64, 256, G1_TOTAL>>>(b1);
    gemm2_mma_kernel<<<dim3(FF / 128, BT / 128), 512, G2_TOTAL>>>(x, b2, out);
    ln_kernel<<<BT, 128>>>(out, gamma, beta);
}